// round 1
// baseline (speedup 1.0000x reference)
#include <cuda_runtime.h>
#include <math.h>

#define HDIM 128
#define EDIM 64
#define TILE 64
#define NT   128
#define MAXN 50000

typedef unsigned long long ull;

// Scratch (allocation-free rule: __device__ globals)
__device__ float g_h[(size_t)MAXN * HDIM];
__device__ float g_agg[(size_t)MAXN * HDIM];
__device__ float g_deg[MAXN];

// ---------- packed f32x2 helpers (Blackwell FFMA2, PTX-only) ----------
__device__ __forceinline__ ull pack2(float v) {
    ull r; asm("mov.b64 %0, {%1, %1};" : "=l"(r) : "f"(v)); return r;
}
__device__ __forceinline__ void fma2(ull& c, ull a, ull b) {
    asm("fma.rn.f32x2 %0, %1, %2, %0;" : "+l"(c) : "l"(a), "l"(b));
}
__device__ __forceinline__ float2 unpack2(ull v) {
    float2 f; asm("mov.b64 {%0, %1}, %2;" : "=f"(f.x), "=f"(f.y) : "l"(v)); return f;
}
__device__ __forceinline__ float gelu_f(float x) {
    return 0.5f * x * (1.0f + erff(x * 0.70710678118654752f));
}

// C[64,128] += A[64,K] @ W[K,128-slice]; thread (tr,tc) owns rows tr*8..+7, cols tc*8..+7.
// Column pairs packed into f32x2 accumulators; W pairs are memory-adjacent -> direct u64 loads.
template<int K, int LDA, int LDW>
__device__ __forceinline__ void gemm_acc(ull c2[8][4], const float* __restrict__ As,
                                         const float* __restrict__ W, int tr, int tc) {
    const float* Ab = As + tr * 8 * LDA;
    const float* Wb = W + tc * 8;
#pragma unroll 4
    for (int k = 0; k < K; k++) {
        const ull* wp = (const ull*)(Wb + (size_t)k * LDW);
        ull w0 = __ldg(wp + 0), w1 = __ldg(wp + 1), w2 = __ldg(wp + 2), w3 = __ldg(wp + 3);
#pragma unroll
        for (int i = 0; i < 8; i++) {
            ull a2 = pack2(Ab[i * LDA + k]);
            fma2(c2[i][0], a2, w0);
            fma2(c2[i][1], a2, w1);
            fma2(c2[i][2], a2, w2);
            fma2(c2[i][3], a2, w3);
        }
    }
}

__device__ __forceinline__ void zero_acc(ull c2[8][4]) {
#pragma unroll
    for (int i = 0; i < 8; i++)
#pragma unroll
        for (int p = 0; p < 4; p++) c2[i][p] = 0ull;
}

// store gelu(C + bias) into smem dst (row stride LDS)
template<int LDS>
__device__ __forceinline__ void epi_gelu(ull c2[8][4], float* dst, const float* __restrict__ bias,
                                         int tr, int tc) {
    float b[8];
#pragma unroll
    for (int j = 0; j < 8; j++) b[j] = __ldg(bias + tc * 8 + j);
#pragma unroll
    for (int i = 0; i < 8; i++) {
        int r = tr * 8 + i;
        float v[8];
#pragma unroll
        for (int p = 0; p < 4; p++) { float2 f = unpack2(c2[i][p]); v[2 * p] = f.x; v[2 * p + 1] = f.y; }
        float4 o0 = make_float4(gelu_f(v[0] + b[0]), gelu_f(v[1] + b[1]),
                                gelu_f(v[2] + b[2]), gelu_f(v[3] + b[3]));
        float4 o1 = make_float4(gelu_f(v[4] + b[4]), gelu_f(v[5] + b[5]),
                                gelu_f(v[6] + b[6]), gelu_f(v[7] + b[7]));
        *(float4*)(dst + r * LDS + tc * 8)     = o0;
        *(float4*)(dst + r * LDS + tc * 8 + 4) = o1;
    }
}

// ---------------- Kernel 1: LN(x) -> g_h, zero agg/deg ----------------
__global__ void ln1_zero_kernel(const float* __restrict__ x,
                                const float* __restrict__ g, const float* __restrict__ b, int n) {
    int row = blockIdx.x * 8 + (threadIdx.x >> 5);
    int lane = threadIdx.x & 31;
    if (row >= n) return;
    float4 v = ((const float4*)(x + (size_t)row * HDIM))[lane];
    float s = v.x + v.y + v.z + v.w;
#pragma unroll
    for (int o = 16; o; o >>= 1) s += __shfl_xor_sync(0xffffffffu, s, o);
    float m = s * (1.0f / 128.0f);
    float dx = v.x - m, dy = v.y - m, dz = v.z - m, dw = v.w - m;
    float q = dx * dx + dy * dy + dz * dz + dw * dw;
#pragma unroll
    for (int o = 16; o; o >>= 1) q += __shfl_xor_sync(0xffffffffu, q, o);
    float rstd = rsqrtf(q * (1.0f / 128.0f) + 1e-5f);
    float4 gv = ((const float4*)g)[lane];
    float4 bv = ((const float4*)b)[lane];
    float4 h;
    h.x = dx * rstd * gv.x + bv.x;
    h.y = dy * rstd * gv.y + bv.y;
    h.z = dz * rstd * gv.z + bv.z;
    h.w = dw * rstd * gv.w + bv.w;
    ((float4*)(g_h + (size_t)row * HDIM))[lane] = h;
    float4 z = make_float4(0.f, 0.f, 0.f, 0.f);
    ((float4*)(g_agg + (size_t)row * HDIM))[lane] = z;
    if (lane == 0) g_deg[row] = 0.0f;
}

// ---------------- Kernel 2: edge MLPs + scatter ----------------
__global__ __launch_bounds__(NT) void edge_kernel(
    const int* __restrict__ esrc, const int* __restrict__ edst,
    const float* __restrict__ eemb,
    const float* __restrict__ Wm1, const float* __restrict__ bm1,
    const float* __restrict__ Wm2, const float* __restrict__ bm2,
    const float* __restrict__ Wg1, const float* __restrict__ bg1,
    const float* __restrict__ Wg2, const float* __restrict__ bg2,
    float* __restrict__ out_edge, int E_) {
    extern __shared__ float sm[];
    float* A  = sm;                         // 64 x 192  ([hs || e])
    float* HD = sm + TILE * 192;            // 64 x 128  (hd, then reused as hidden buffer)
    int*   es = (int*)(HD + TILE * 128);
    int*   ed = es + TILE;
    float* gate = (float*)(ed + TILE);

    int tid = threadIdx.x;
    int tc = tid & 15, tr = tid >> 4;
    long long e0 = (long long)blockIdx.x * TILE;

    if (tid < TILE) {
        long long eg = e0 + tid; if (eg >= E_) eg = E_ - 1;
        es[tid] = esrc[eg]; ed[tid] = edst[eg];
    }
    __syncthreads();

    for (int idx = tid; idx < TILE * 32; idx += NT) {
        int e = idx >> 5, q = idx & 31;
        ((float4*)(A + e * 192))[q]  = ((const float4*)(g_h + (size_t)es[e] * HDIM))[q];
        ((float4*)(HD + e * 128))[q] = ((const float4*)(g_h + (size_t)ed[e] * HDIM))[q];
    }
    for (int idx = tid; idx < TILE * 16; idx += NT) {
        int e = idx >> 4, q = idx & 15;
        long long eg = e0 + e; if (eg >= E_) eg = E_ - 1;
        ((float4*)(A + e * 192 + 128))[q] = ((const float4*)(eemb + eg * EDIM))[q];
    }
    __syncthreads();

    ull c2[8][4];

    // gate hidden: gelu([hd||hs||e] @ Wg1 + bg1) -> HD (reuse)
    zero_acc(c2);
    gemm_acc<128, 128, 128>(c2, HD, Wg1, tr, tc);
    gemm_acc<192, 192, 128>(c2, A,  Wg1 + 128 * 128, tr, tc);
    __syncthreads();                       // all HD reads done before overwrite
    epi_gelu<128>(c2, HD, bg1, tr, tc);
    __syncthreads();

    // gate scalar: sigmoid(Zg . Wg2 + bg2)
    {
        int w = tid >> 5, lane = tid & 31;
        float wg0 = __ldg(Wg2 + lane),      wg1 = __ldg(Wg2 + lane + 32);
        float wg2 = __ldg(Wg2 + lane + 64), wg3 = __ldg(Wg2 + lane + 96);
        float bb = __ldg(bg2);
        for (int e = w; e < TILE; e += 4) {
            const float* z = HD + e * 128;
            float s = z[lane] * wg0 + z[lane + 32] * wg1 + z[lane + 64] * wg2 + z[lane + 96] * wg3;
#pragma unroll
            for (int o = 16; o; o >>= 1) s += __shfl_down_sync(0xffffffffu, s, o);
            if (lane == 0) gate[e] = 1.0f / (1.0f + expf(-(s + bb)));
        }
    }
    __syncthreads();                       // gate reads done before HD overwrite

    // msg hidden: gelu([hs||e] @ Wm1 + bm1) -> HD (reuse)
    zero_acc(c2);
    gemm_acc<192, 192, 128>(c2, A, Wm1, tr, tc);
    __syncthreads();
    epi_gelu<128>(c2, HD, bm1, tr, tc);
    __syncthreads();

    // msg out: (Z1 @ Wm2 + bm2) * gate -> edge_repr + scatter-add
    zero_acc(c2);
    gemm_acc<128, 128, 128>(c2, HD, Wm2, tr, tc);
    {
        float b[8];
#pragma unroll
        for (int j = 0; j < 8; j++) b[j] = __ldg(bm2 + tc * 8 + j);
#pragma unroll
        for (int i = 0; i < 8; i++) {
            int r = tr * 8 + i;
            long long eg = e0 + r;
            if (eg < E_) {
                float g = gate[r];
                float v[8];
#pragma unroll
                for (int p = 0; p < 4; p++) { float2 f = unpack2(c2[i][p]); v[2 * p] = f.x; v[2 * p + 1] = f.y; }
#pragma unroll
                for (int j = 0; j < 8; j++) v[j] = (v[j] + b[j]) * g;
                float4 o0 = make_float4(v[0], v[1], v[2], v[3]);
                float4 o1 = make_float4(v[4], v[5], v[6], v[7]);
                *(float4*)(out_edge + eg * HDIM + tc * 8)     = o0;
                *(float4*)(out_edge + eg * HDIM + tc * 8 + 4) = o1;
                float* ag = g_agg + (size_t)ed[r] * HDIM + tc * 8;
                atomicAdd(ag + 0, v[0]); atomicAdd(ag + 1, v[1]);
                atomicAdd(ag + 2, v[2]); atomicAdd(ag + 3, v[3]);
                atomicAdd(ag + 4, v[4]); atomicAdd(ag + 5, v[5]);
                atomicAdd(ag + 6, v[6]); atomicAdd(ag + 7, v[7]);
            }
        }
    }
    if (tid < TILE && e0 + tid < E_) atomicAdd(&g_deg[ed[tid]], 1.0f);
}

// ---------------- Kernel 3: node update + FFN ----------------
__global__ __launch_bounds__(NT) void node_kernel(
    const float* __restrict__ x,
    const float* __restrict__ Wself, const float* __restrict__ bself,
    const float* __restrict__ Wagg,  const float* __restrict__ bagg,
    const float* __restrict__ ln2g,  const float* __restrict__ ln2b,
    const float* __restrict__ Wf1,   const float* __restrict__ bf1,
    const float* __restrict__ Wf2,   const float* __restrict__ bf2,
    float* __restrict__ out, int n) {
    extern __shared__ float sm[];
    float* XH  = sm;                        // 64 x 128 (h, later FIN)
    float* AG  = XH + TILE * 128;           // 64 x 128
    float* OUT = AG + TILE * 128;           // 64 x 128
    float* T   = OUT + TILE * 128;          // 64 x 256
    float* muv = T + TILE * 256;            // 64
    float* rsv = muv + TILE;                // 64

    int tid = threadIdx.x;
    int tc = tid & 15, tr = tid >> 4;
    int n0 = blockIdx.x * TILE;

    for (int idx = tid; idx < TILE * 32; idx += NT) {
        int r = idx >> 5, q = idx & 31;
        int nn = n0 + r; if (nn >= n) nn = n - 1;
        ((float4*)(XH + r * 128))[q] = ((const float4*)(g_h + (size_t)nn * HDIM))[q];
        float4 a = ((const float4*)(g_agg + (size_t)nn * HDIM))[q];
        float d = fmaxf(g_deg[nn], 1.0f);
        float inv = 1.0f / d;
        a.x *= inv; a.y *= inv; a.z *= inv; a.w *= inv;
        ((float4*)(AG + r * 128))[q] = a;
    }
    __syncthreads();

    ull c2[8][4];
    // update = h@Wself + agg@Wagg + biases + x -> OUT
    zero_acc(c2);
    gemm_acc<128, 128, 128>(c2, XH, Wself, tr, tc);
    gemm_acc<128, 128, 128>(c2, AG, Wagg,  tr, tc);
    {
        float b[8];
#pragma unroll
        for (int j = 0; j < 8; j++) b[j] = __ldg(bself + tc * 8 + j) + __ldg(bagg + tc * 8 + j);
#pragma unroll
        for (int i = 0; i < 8; i++) {
            int r = tr * 8 + i;
            int nn = n0 + r; if (nn >= n) nn = n - 1;
            float4 x0 = __ldg((const float4*)(x + (size_t)nn * HDIM + tc * 8));
            float4 x1 = __ldg((const float4*)(x + (size_t)nn * HDIM + tc * 8 + 4));
            float v[8];
#pragma unroll
            for (int p = 0; p < 4; p++) { float2 f = unpack2(c2[i][p]); v[2 * p] = f.x; v[2 * p + 1] = f.y; }
            float4 o0 = make_float4(v[0] + b[0] + x0.x, v[1] + b[1] + x0.y,
                                    v[2] + b[2] + x0.z, v[3] + b[3] + x0.w);
            float4 o1 = make_float4(v[4] + b[4] + x1.x, v[5] + b[5] + x1.y,
                                    v[6] + b[6] + x1.z, v[7] + b[7] + x1.w);
            *(float4*)(OUT + r * 128 + tc * 8)     = o0;
            *(float4*)(OUT + r * 128 + tc * 8 + 4) = o1;
        }
    }
    __syncthreads();

    // LN2 stats (warp per 16 rows)
    {
        int w = tid >> 5, lane = tid & 31;
        for (int r = w; r < TILE; r += 4) {
            const float* o = OUT + r * 128;
            float v0 = o[lane], v1 = o[lane + 32], v2 = o[lane + 64], v3 = o[lane + 96];
            float s = v0 + v1 + v2 + v3;
#pragma unroll
            for (int of = 16; of; of >>= 1) s += __shfl_xor_sync(0xffffffffu, s, of);
            float m = s * (1.0f / 128.0f);
            float d0 = v0 - m, d1 = v1 - m, d2 = v2 - m, d3 = v3 - m;
            float q = d0 * d0 + d1 * d1 + d2 * d2 + d3 * d3;
#pragma unroll
            for (int of = 16; of; of >>= 1) q += __shfl_xor_sync(0xffffffffu, q, of);
            if (lane == 0) { muv[r] = m; rsv[r] = rsqrtf(q * (1.0f / 128.0f) + 1e-5f); }
        }
    }
    __syncthreads();
    for (int idx = tid; idx < TILE * 128; idx += NT) {
        int r = idx >> 7, c = idx & 127;
        XH[idx] = (OUT[idx] - muv[r]) * rsv[r] * __ldg(ln2g + c) + __ldg(ln2b + c);
    }
    __syncthreads();

    // FFN up: gelu(FIN @ Wf1 + bf1) -> T [64,256], two column halves
#pragma unroll 1
    for (int half = 0; half < 2; half++) {
        zero_acc(c2);
        gemm_acc<128, 128, 256>(c2, XH, Wf1 + half * 128, tr, tc);
        float b[8];
#pragma unroll
        for (int j = 0; j < 8; j++) b[j] = __ldg(bf1 + half * 128 + tc * 8 + j);
#pragma unroll
        for (int i = 0; i < 8; i++) {
            int r = tr * 8 + i;
            float v[8];
#pragma unroll
            for (int p = 0; p < 4; p++) { float2 f = unpack2(c2[i][p]); v[2 * p] = f.x; v[2 * p + 1] = f.y; }
            float4 o0 = make_float4(gelu_f(v[0] + b[0]), gelu_f(v[1] + b[1]),
                                    gelu_f(v[2] + b[2]), gelu_f(v[3] + b[3]));
            float4 o1 = make_float4(gelu_f(v[4] + b[4]), gelu_f(v[5] + b[5]),
                                    gelu_f(v[6] + b[6]), gelu_f(v[7] + b[7]));
            *(float4*)(T + r * 256 + half * 128 + tc * 8)     = o0;
            *(float4*)(T + r * 256 + half * 128 + tc * 8 + 4) = o1;
        }
    }
    __syncthreads();

    // FFN down + residual -> out
    zero_acc(c2);
    gemm_acc<256, 256, 128>(c2, T, Wf2, tr, tc);
    {
        float b[8];
#pragma unroll
        for (int j = 0; j < 8; j++) b[j] = __ldg(bf2 + tc * 8 + j);
#pragma unroll
        for (int i = 0; i < 8; i++) {
            int r = tr * 8 + i;
            int nn = n0 + r;
            if (nn < n) {
                float v[8];
#pragma unroll
                for (int p = 0; p < 4; p++) { float2 f = unpack2(c2[i][p]); v[2 * p] = f.x; v[2 * p + 1] = f.y; }
#pragma unroll
                for (int j = 0; j < 8; j++) v[j] = v[j] + b[j] + OUT[r * 128 + tc * 8 + j];
                float4 o0 = make_float4(v[0], v[1], v[2], v[3]);
                float4 o1 = make_float4(v[4], v[5], v[6], v[7]);
                *(float4*)(out + (size_t)nn * HDIM + tc * 8)     = o0;
                *(float4*)(out + (size_t)nn * HDIM + tc * 8 + 4) = o1;
            }
        }
    }
}

// ---------------- launch ----------------
extern "C" void kernel_launch(void* const* d_in, const int* in_sizes, int n_in,
                              void* d_out, int out_size) {
    const float* x     = (const float*)d_in[0];
    const int*   esrc  = (const int*)d_in[1];
    const int*   edst  = (const int*)d_in[2];
    const float* eemb  = (const float*)d_in[3];
    const float* ln1g  = (const float*)d_in[4];
    const float* ln1b  = (const float*)d_in[5];
    const float* Wself = (const float*)d_in[6];
    const float* bself = (const float*)d_in[7];
    const float* Wm1   = (const float*)d_in[8];
    const float* bm1   = (const float*)d_in[9];
    const float* Wm2   = (const float*)d_in[10];
    const float* bm2   = (const float*)d_in[11];
    const float* Wg1   = (const float*)d_in[12];
    const float* bg1   = (const float*)d_in[13];
    const float* Wg2   = (const float*)d_in[14];
    const float* bg2   = (const float*)d_in[15];
    const float* Wagg  = (const float*)d_in[16];
    const float* bagg  = (const float*)d_in[17];
    const float* ln2g  = (const float*)d_in[18];
    const float* ln2b  = (const float*)d_in[19];
    const float* Wf1   = (const float*)d_in[20];
    const float* bf1   = (const float*)d_in[21];
    const float* Wf2   = (const float*)d_in[22];
    const float* bf2   = (const float*)d_in[23];

    int n = in_sizes[0] / HDIM;
    int E = in_sizes[1];
    float* out      = (float*)d_out;
    float* out_edge = out + (size_t)n * HDIM;

    const int EDGE_SMEM = (TILE * 192 + TILE * 128) * 4 + TILE * 4 * 3;
    const int NODE_SMEM = (TILE * 128 * 3 + TILE * 256 + 2 * TILE) * 4;
    cudaFuncSetAttribute(edge_kernel, cudaFuncAttributeMaxDynamicSharedMemorySize, EDGE_SMEM);
    cudaFuncSetAttribute(node_kernel, cudaFuncAttributeMaxDynamicSharedMemorySize, NODE_SMEM);

    ln1_zero_kernel<<<(n + 7) / 8, 256>>>(x, ln1g, ln1b, n);
    edge_kernel<<<(E + TILE - 1) / TILE, NT, EDGE_SMEM>>>(
        esrc, edst, eemb, Wm1, bm1, Wm2, bm2, Wg1, bg1, Wg2, bg2, out_edge, E);
    node_kernel<<<(n + TILE - 1) / TILE, NT, NODE_SMEM>>>(
        x, Wself, bself, Wagg, bagg, ln2g, ln2b, Wf1, bf1, Wf2, bf2, out, n);
}

// round 5
// speedup vs baseline: 2.1844x; 2.1844x over previous
#include <cuda_runtime.h>
#include <math.h>
#include <stdint.h>

#define HDIM 128
#define EDIM 64
#define MAXN 50000
#define ASTRIDE 324   // 320 K + 4 pad; 324 % 32 == 4 -> conflict-free frag loads

typedef unsigned long long ull;

// ---------------- device scratch (allocation-free rule) ----------------
__device__ float g_h[(size_t)MAXN * HDIM];
__device__ float g_agg[(size_t)MAXN * HDIM];
__device__ float g_deg[MAXN];
// tf32-rounded weights, [k][n] row-major: rows 0-319 Wg1, 320-511 Wm1, 512-639 Wm2
__device__ uint32_t g_Wr[640 * 128];

// ---------------- helpers ----------------
__device__ __forceinline__ float gelu_f(float x) {
    return 0.5f * x * (1.0f + erff(x * 0.70710678118654752f));
}
__device__ __forceinline__ float rtf(float v) {   // round f32 -> tf32 (rna)
    uint32_t u; asm("cvt.rna.tf32.f32 %0, %1;" : "=r"(u) : "f"(v));
    return __uint_as_float(u);
}
__device__ __forceinline__ ull pack2(float v) {
    ull r; asm("mov.b64 %0, {%1, %1};" : "=l"(r) : "f"(v)); return r;
}
__device__ __forceinline__ void fma2(ull& c, ull a, ull b) {
    asm("fma.rn.f32x2 %0, %1, %2, %0;" : "+l"(c) : "l"(a), "l"(b));
}
__device__ __forceinline__ float2 unpack2(ull v) {
    float2 f; asm("mov.b64 {%0, %1}, %2;" : "=f"(f.x), "=f"(f.y) : "l"(v)); return f;
}
__device__ __forceinline__ void mma8(float* d, const uint32_t* a, const uint32_t* b) {
    asm volatile("mma.sync.aligned.m16n8k8.row.col.f32.tf32.tf32.f32 "
                 "{%0,%1,%2,%3}, {%4,%5,%6,%7}, {%8,%9}, {%0,%1,%2,%3};"
                 : "+f"(d[0]), "+f"(d[1]), "+f"(d[2]), "+f"(d[3])
                 : "r"(a[0]), "r"(a[1]), "r"(a[2]), "r"(a[3]), "r"(b[0]), "r"(b[1]));
}

__device__ __forceinline__ void zeroD(float D[2][8][4]) {
#pragma unroll
    for (int mt = 0; mt < 2; ++mt)
#pragma unroll
        for (int nt = 0; nt < 8; ++nt)
#pragma unroll
            for (int j = 0; j < 4; ++j) D[mt][nt][j] = 0.0f;
}

// Warp GEMM: D[32x64] += As[rows rbase..rbase+31][acol0 .. acol0+8*ksteps) @ W
// W is tf32 [k][128] row-major; warp covers cols cbase..cbase+63.
__device__ __forceinline__ void wgemm(float D[2][8][4], const float* As, int acol0, int ksteps,
                                      const uint32_t* W, int rbase, int cbase, int g, int t) {
    const float* Ap = As + (rbase + g) * ASTRIDE + acol0 + t;
    const uint32_t* Wp = W + t * 128 + cbase + g;
#pragma unroll 4
    for (int k = 0; k < ksteps; ++k) {
        uint32_t a[2][4], b[8][2];
        int ao = k * 8;
#pragma unroll
        for (int mt = 0; mt < 2; ++mt) {
            const float* Am = Ap + mt * 16 * ASTRIDE;
            a[mt][0] = __float_as_uint(Am[ao]);
            a[mt][1] = __float_as_uint(Am[8 * ASTRIDE + ao]);
            a[mt][2] = __float_as_uint(Am[ao + 4]);
            a[mt][3] = __float_as_uint(Am[8 * ASTRIDE + ao + 4]);
        }
        const uint32_t* Wk = Wp + k * 1024;    // 8 k-rows * 128
#pragma unroll
        for (int nt = 0; nt < 8; ++nt) {
            b[nt][0] = __ldg(Wk + nt * 8);
            b[nt][1] = __ldg(Wk + 512 + nt * 8);
        }
#pragma unroll
        for (int mt = 0; mt < 2; ++mt)
#pragma unroll
            for (int nt = 0; nt < 8; ++nt)
                mma8(D[mt][nt], a[mt], b[nt]);
    }
}

// ---------------- Kernel 0: round weights to tf32 ----------------
__global__ void prep_wt_kernel(const float* __restrict__ Wg1,
                               const float* __restrict__ Wm1,
                               const float* __restrict__ Wm2) {
    int idx = blockIdx.x * 256 + threadIdx.x;
    if (idx >= 640 * 128) return;
    int k = idx >> 7, n = idx & 127;
    float v;
    if (k < 320)      v = Wg1[k * 128 + n];
    else if (k < 512) v = Wm1[(k - 320) * 128 + n];
    else              v = Wm2[(k - 512) * 128 + n];
    uint32_t u; asm("cvt.rna.tf32.f32 %0, %1;" : "=r"(u) : "f"(v));
    g_Wr[idx] = u;
}

// ---------------- Kernel 1: LN(x) -> g_h, zero agg/deg ----------------
__global__ void ln1_zero_kernel(const float* __restrict__ x,
                                const float* __restrict__ g, const float* __restrict__ b, int n) {
    int row = blockIdx.x * 8 + (threadIdx.x >> 5);
    int lane = threadIdx.x & 31;
    if (row >= n) return;
    float4 v = ((const float4*)(x + (size_t)row * HDIM))[lane];
    float s = v.x + v.y + v.z + v.w;
#pragma unroll
    for (int o = 16; o; o >>= 1) s += __shfl_xor_sync(0xffffffffu, s, o);
    float m = s * (1.0f / 128.0f);
    float dx = v.x - m, dy = v.y - m, dz = v.z - m, dw = v.w - m;
    float q = dx * dx + dy * dy + dz * dz + dw * dw;
#pragma unroll
    for (int o = 16; o; o >>= 1) q += __shfl_xor_sync(0xffffffffu, q, o);
    float rstd = rsqrtf(q * (1.0f / 128.0f) + 1e-5f);
    float4 gv = ((const float4*)g)[lane];
    float4 bv = ((const float4*)b)[lane];
    float4 h;
    h.x = dx * rstd * gv.x + bv.x;
    h.y = dy * rstd * gv.y + bv.y;
    h.z = dz * rstd * gv.z + bv.z;
    h.w = dw * rstd * gv.w + bv.w;
    ((float4*)(g_h + (size_t)row * HDIM))[lane] = h;
    ((float4*)(g_agg + (size_t)row * HDIM))[lane] = make_float4(0.f, 0.f, 0.f, 0.f);
    if (lane == 0) g_deg[row] = 0.0f;
}

// ---------------- Kernel 2: edge MLPs via mma.sync tf32 ----------------
// 128 edges/block, 256 threads; warp (mw,nw): rows mw*32..+32, cols nw*64..+64.
__global__ __launch_bounds__(256, 1) void edge_kernel(
    const int* __restrict__ esrc, const int* __restrict__ edst,
    const float* __restrict__ eemb,
    const float* __restrict__ bg1, const float* __restrict__ Wg2, const float* __restrict__ bg2,
    const float* __restrict__ bm1, const float* __restrict__ bm2,
    float* __restrict__ out_edge, int E_) {
    extern __shared__ float sm[];
    float* As = sm;                      // 128 x 324: [hd | hs | e], hd zone reused for Z
    float* gs = sm + 128 * ASTRIDE;      // 128 gate pre-activations
    int* esm = (int*)(gs + 128);
    int* edm = esm + 128;

    int tid = threadIdx.x, lane = tid & 31, wid = tid >> 5;
    int g = lane >> 2, t = lane & 3;
    int mw = wid >> 1, nw = wid & 1;
    int rbase = mw * 32, cbase = nw * 64;
    long long e0 = (long long)blockIdx.x * 128;

    if (tid < 128) {
        long long eg = e0 + tid;
        int cl = (eg < E_) ? (int)eg : (E_ - 1);
        int s = esrc[cl], d = edst[cl];
        esm[tid] = s; edm[tid] = d; gs[tid] = 0.0f;
        if (eg < E_) atomicAdd(&g_deg[d], 1.0f);
    }
    __syncthreads();

    // gather (tf32-rounded): hd -> cols 0-127, hs -> 128-255, e -> 256-319
    for (int idx = tid; idx < 128 * 32; idx += 256) {
        int r = idx >> 5, q = idx & 31;
        float4 vd = ((const float4*)(g_h + (size_t)edm[r] * HDIM))[q];
        float4 vs = ((const float4*)(g_h + (size_t)esm[r] * HDIM))[q];
        float* dst = As + r * ASTRIDE + q * 4;
        dst[0] = rtf(vd.x); dst[1] = rtf(vd.y); dst[2] = rtf(vd.z); dst[3] = rtf(vd.w);
        dst[128] = rtf(vs.x); dst[129] = rtf(vs.y); dst[130] = rtf(vs.z); dst[131] = rtf(vs.w);
    }
    for (int idx = tid; idx < 128 * 16; idx += 256) {
        int r = idx >> 4, q = idx & 15;
        long long eg = e0 + r; if (eg >= E_) eg = E_ - 1;
        float4 ve = ((const float4*)(eemb + eg * (long long)EDIM))[q];
        float* dst = As + r * ASTRIDE + 256 + q * 4;
        dst[0] = rtf(ve.x); dst[1] = rtf(ve.y); dst[2] = rtf(ve.z); dst[3] = rtf(ve.w);
    }
    __syncthreads();

    float D[2][8][4];

    // ---- gate hidden: [hd|hs|e] @ Wg1, reduced in-register to gs[row] ----
    zeroD(D);
    wgemm(D, As, 0, 40, g_Wr, rbase, cbase, g, t);
#pragma unroll
    for (int mt = 0; mt < 2; ++mt) {
        float s0 = 0.f, s1 = 0.f;
#pragma unroll
        for (int nt = 0; nt < 8; ++nt) {
            int c = cbase + nt * 8 + t * 2;
            float w0 = __ldg(Wg2 + c), w1 = __ldg(Wg2 + c + 1);
            float b0 = __ldg(bg1 + c), b1 = __ldg(bg1 + c + 1);
            s0 += gelu_f(D[mt][nt][0] + b0) * w0 + gelu_f(D[mt][nt][1] + b1) * w1;
            s1 += gelu_f(D[mt][nt][2] + b0) * w0 + gelu_f(D[mt][nt][3] + b1) * w1;
        }
        s0 += __shfl_xor_sync(0xffffffffu, s0, 1); s0 += __shfl_xor_sync(0xffffffffu, s0, 2);
        s1 += __shfl_xor_sync(0xffffffffu, s1, 1); s1 += __shfl_xor_sync(0xffffffffu, s1, 2);
        if (t == 0) {
            atomicAdd(&gs[rbase + mt * 16 + g], s0);
            atomicAdd(&gs[rbase + mt * 16 + 8 + g], s1);
        }
    }

    // ---- msg1 hidden: [hs|e] @ Wm1 (reads cols 128-319 only) ----
    zeroD(D);
    wgemm(D, As, 128, 24, g_Wr + 320 * 128, rbase, cbase, g, t);
    __syncthreads();   // all gate reads of hd done; gs atomics visible

    // Z = gelu(msg1 + bm1) overwrites hd zone (cols 0-127), tf32-rounded
#pragma unroll
    for (int mt = 0; mt < 2; ++mt)
#pragma unroll
        for (int nt = 0; nt < 8; ++nt) {
            int c = cbase + nt * 8 + t * 2;
            float b0 = __ldg(bm1 + c), b1 = __ldg(bm1 + c + 1);
            int r0 = rbase + mt * 16 + g;
            *(float2*)(As + r0 * ASTRIDE + c) =
                make_float2(rtf(gelu_f(D[mt][nt][0] + b0)), rtf(gelu_f(D[mt][nt][1] + b1)));
            *(float2*)(As + (r0 + 8) * ASTRIDE + c) =
                make_float2(rtf(gelu_f(D[mt][nt][2] + b0)), rtf(gelu_f(D[mt][nt][3] + b1)));
        }
    __syncthreads();

    // ---- msg2: Z @ Wm2 ----
    zeroD(D);
    wgemm(D, As, 0, 16, g_Wr + 512 * 128, rbase, cbase, g, t);

    // ---- epilogue: edge_repr = (msg2 + bm2) * sigmoid(gate); scatter-add ----
    float bg2v = __ldg(bg2);
#pragma unroll
    for (int mt = 0; mt < 2; ++mt) {
        int r0 = rbase + mt * 16 + g, r1 = r0 + 8;
        float gt0 = 1.0f / (1.0f + expf(-(gs[r0] + bg2v)));
        float gt1 = 1.0f / (1.0f + expf(-(gs[r1] + bg2v)));
        long long eg0 = e0 + r0, eg1 = e0 + r1;
        int d0 = edm[r0], d1 = edm[r1];
#pragma unroll
        for (int nt = 0; nt < 8; ++nt) {
            int c = cbase + nt * 8 + t * 2;
            float b0 = __ldg(bm2 + c), b1 = __ldg(bm2 + c + 1);
            if (eg0 < E_) {
                float v0 = (D[mt][nt][0] + b0) * gt0, v1 = (D[mt][nt][1] + b1) * gt0;
                *(float2*)(out_edge + eg0 * 128 + c) = make_float2(v0, v1);
                atomicAdd(g_agg + (size_t)d0 * 128 + c, v0);
                atomicAdd(g_agg + (size_t)d0 * 128 + c + 1, v1);
            }
            if (eg1 < E_) {
                float v2 = (D[mt][nt][2] + b0) * gt1, v3 = (D[mt][nt][3] + b1) * gt1;
                *(float2*)(out_edge + eg1 * 128 + c) = make_float2(v2, v3);
                atomicAdd(g_agg + (size_t)d1 * 128 + c, v2);
                atomicAdd(g_agg + (size_t)d1 * 128 + c + 1, v3);
            }
        }
    }
}

// ---------------- scalar GEMM core for node kernel (f32x2) ----------------
template<int K, int LDA, int LDW>
__device__ __forceinline__ void gemm_acc(ull c2[8][4], const float* __restrict__ As,
                                         const float* __restrict__ W, int tr, int tc) {
    const float* Ab = As + tr * 8 * LDA;
    const float* Wb = W + tc * 8;
#pragma unroll 4
    for (int k = 0; k < K; k++) {
        const ull* wp = (const ull*)(Wb + (size_t)k * LDW);
        ull w0 = __ldg(wp + 0), w1 = __ldg(wp + 1), w2 = __ldg(wp + 2), w3 = __ldg(wp + 3);
#pragma unroll
        for (int i = 0; i < 8; i++) {
            ull a2 = pack2(Ab[i * LDA + k]);
            fma2(c2[i][0], a2, w0); fma2(c2[i][1], a2, w1);
            fma2(c2[i][2], a2, w2); fma2(c2[i][3], a2, w3);
        }
    }
}
__device__ __forceinline__ void zero_acc(ull c2[8][4]) {
#pragma unroll
    for (int i = 0; i < 8; i++)
#pragma unroll
        for (int p = 0; p < 4; p++) c2[i][p] = 0ull;
}

#define NTILE 64
#define NNT   128

__global__ __launch_bounds__(NNT) void node_kernel(
    const float* __restrict__ x,
    const float* __restrict__ Wself, const float* __restrict__ bself,
    const float* __restrict__ Wagg,  const float* __restrict__ bagg,
    const float* __restrict__ ln2g,  const float* __restrict__ ln2b,
    const float* __restrict__ Wf1,   const float* __restrict__ bf1,
    const float* __restrict__ Wf2,   const float* __restrict__ bf2,
    float* __restrict__ out, int n) {
    extern __shared__ float sm[];
    float* XH  = sm;
    float* AG  = XH + NTILE * 128;
    float* OUT = AG + NTILE * 128;
    float* T   = OUT + NTILE * 128;
    float* muv = T + NTILE * 256;
    float* rsv = muv + NTILE;

    int tid = threadIdx.x;
    int tc = tid & 15, tr = tid >> 4;
    int n0 = blockIdx.x * NTILE;

    for (int idx = tid; idx < NTILE * 32; idx += NNT) {
        int r = idx >> 5, q = idx & 31;
        int nn = n0 + r; if (nn >= n) nn = n - 1;
        ((float4*)(XH + r * 128))[q] = ((const float4*)(g_h + (size_t)nn * HDIM))[q];
        float4 a = ((const float4*)(g_agg + (size_t)nn * HDIM))[q];
        float inv = 1.0f / fmaxf(g_deg[nn], 1.0f);
        a.x *= inv; a.y *= inv; a.z *= inv; a.w *= inv;
        ((float4*)(AG + r * 128))[q] = a;
    }
    __syncthreads();

    ull c2[8][4];
    zero_acc(c2);
    gemm_acc<128, 128, 128>(c2, XH, Wself, tr, tc);
    gemm_acc<128, 128, 128>(c2, AG, Wagg,  tr, tc);
    {
        float b[8];
#pragma unroll
        for (int j = 0; j < 8; j++) b[j] = __ldg(bself + tc * 8 + j) + __ldg(bagg + tc * 8 + j);
#pragma unroll
        for (int i = 0; i < 8; i++) {
            int r = tr * 8 + i;
            int nn = n0 + r; if (nn >= n) nn = n - 1;
            float4 x0 = __ldg((const float4*)(x + (size_t)nn * HDIM + tc * 8));
            float4 x1 = __ldg((const float4*)(x + (size_t)nn * HDIM + tc * 8 + 4));
            float v[8];
#pragma unroll
            for (int p = 0; p < 4; p++) { float2 f = unpack2(c2[i][p]); v[2*p] = f.x; v[2*p+1] = f.y; }
            *(float4*)(OUT + r * 128 + tc * 8)     = make_float4(v[0]+b[0]+x0.x, v[1]+b[1]+x0.y, v[2]+b[2]+x0.z, v[3]+b[3]+x0.w);
            *(float4*)(OUT + r * 128 + tc * 8 + 4) = make_float4(v[4]+b[4]+x1.x, v[5]+b[5]+x1.y, v[6]+b[6]+x1.z, v[7]+b[7]+x1.w);
        }
    }
    __syncthreads();

    {
        int w = tid >> 5, lane = tid & 31;
        for (int r = w; r < NTILE; r += 4) {
            const float* o = OUT + r * 128;
            float v0 = o[lane], v1 = o[lane + 32], v2 = o[lane + 64], v3 = o[lane + 96];
            float s = v0 + v1 + v2 + v3;
#pragma unroll
            for (int of = 16; of; of >>= 1) s += __shfl_xor_sync(0xffffffffu, s, of);
            float m = s * (1.0f / 128.0f);
            float d0 = v0 - m, d1 = v1 - m, d2 = v2 - m, d3 = v3 - m;
            float q = d0*d0 + d1*d1 + d2*d2 + d3*d3;
#pragma unroll
            for (int of = 16; of; of >>= 1) q += __shfl_xor_sync(0xffffffffu, q, of);
            if (lane == 0) { muv[r] = m; rsv[r] = rsqrtf(q * (1.0f / 128.0f) + 1e-5f); }
        }
    }
    __syncthreads();
    for (int idx = tid; idx < NTILE * 128; idx += NNT) {
        int r = idx >> 7, c = idx & 127;
        XH[idx] = (OUT[idx] - muv[r]) * rsv[r] * __ldg(ln2g + c) + __ldg(ln2b + c);
    }
    __syncthreads();

#pragma unroll 1
    for (int half = 0; half < 2; half++) {
        zero_acc(c2);
        gemm_acc<128, 128, 256>(c2, XH, Wf1 + half * 128, tr, tc);
        float b[8];
#pragma unroll
        for (int j = 0; j < 8; j++) b[j] = __ldg(bf1 + half * 128 + tc * 8 + j);
#pragma unroll
        for (int i = 0; i < 8; i++) {
            int r = tr * 8 + i;
            float v[8];
#pragma unroll
            for (int p = 0; p < 4; p++) { float2 f = unpack2(c2[i][p]); v[2*p] = f.x; v[2*p+1] = f.y; }
            *(float4*)(T + r * 256 + half * 128 + tc * 8) =
                make_float4(gelu_f(v[0]+b[0]), gelu_f(v[1]+b[1]), gelu_f(v[2]+b[2]), gelu_f(v[3]+b[3]));
            *(float4*)(T + r * 256 + half * 128 + tc * 8 + 4) =
                make_float4(gelu_f(v[4]+b[4]), gelu_f(v[5]+b[5]), gelu_f(v[6]+b[6]), gelu_f(v[7]+b[7]));
        }
    }
    __syncthreads();

    zero_acc(c2);
    gemm_acc<256, 256, 128>(c2, T, Wf2, tr, tc);
    {
        float b[8];
#pragma unroll
        for (int j = 0; j < 8; j++) b[j] = __ldg(bf2 + tc * 8 + j);
#pragma unroll
        for (int i = 0; i < 8; i++) {
            int r = tr * 8 + i;
            int nn = n0 + r;
            if (nn < n) {
                float v[8];
#pragma unroll
                for (int p = 0; p < 4; p++) { float2 f = unpack2(c2[i][p]); v[2*p] = f.x; v[2*p+1] = f.y; }
#pragma unroll
                for (int j = 0; j < 8; j++) v[j] = v[j] + b[j] + OUT[r * 128 + tc * 8 + j];
                *(float4*)(out + (size_t)nn * HDIM + tc * 8)     = make_float4(v[0], v[1], v[2], v[3]);
                *(float4*)(out + (size_t)nn * HDIM + tc * 8 + 4) = make_float4(v[4], v[5], v[6], v[7]);
            }
        }
    }
}

// ---------------- launch ----------------
extern "C" void kernel_launch(void* const* d_in, const int* in_sizes, int n_in,
                              void* d_out, int out_size) {
    const float* x     = (const float*)d_in[0];
    const int*   esrc  = (const int*)d_in[1];
    const int*   edst  = (const int*)d_in[2];
    const float* eemb  = (const float*)d_in[3];
    const float* ln1g  = (const float*)d_in[4];
    const float* ln1b  = (const float*)d_in[5];
    const float* Wself = (const float*)d_in[6];
    const float* bself = (const float*)d_in[7];
    const float* Wm1   = (const float*)d_in[8];
    const float* bm1   = (const float*)d_in[9];
    const float* Wm2   = (const float*)d_in[10];
    const float* bm2   = (const float*)d_in[11];
    const float* Wg1   = (const float*)d_in[12];
    const float* bg1   = (const float*)d_in[13];
    const float* Wg2   = (const float*)d_in[14];
    const float* bg2   = (const float*)d_in[15];
    const float* Wagg  = (const float*)d_in[16];
    const float* bagg  = (const float*)d_in[17];
    const float* ln2g  = (const float*)d_in[18];
    const float* ln2b  = (const float*)d_in[19];
    const float* Wf1   = (const float*)d_in[20];
    const float* bf1   = (const float*)d_in[21];
    const float* Wf2   = (const float*)d_in[22];
    const float* bf2   = (const float*)d_in[23];

    int n = in_sizes[0] / HDIM;
    int E = in_sizes[1];
    float* out      = (float*)d_out;
    float* out_edge = out + (size_t)n * HDIM;

    const int EDGE_SMEM = (128 * ASTRIDE + 128) * 4 + 256 * 4;
    const int NODE_SMEM = (NTILE * 128 * 3 + NTILE * 256 + 2 * NTILE) * 4;
    cudaFuncSetAttribute(edge_kernel, cudaFuncAttributeMaxDynamicSharedMemorySize, EDGE_SMEM);
    cudaFuncSetAttribute(node_kernel, cudaFuncAttributeMaxDynamicSharedMemorySize, NODE_SMEM);

    prep_wt_kernel<<<(640 * 128 + 255) / 256, 256>>>(Wg1, Wm1, Wm2);
    ln1_zero_kernel<<<(n + 7) / 8, 256>>>(x, ln1g, ln1b, n);
    edge_kernel<<<(E + 127) / 128, 256, EDGE_SMEM>>>(
        esrc, edst, eemb, bg1, Wg2, bg2, bm1, bm2, out_edge, E);
    node_kernel<<<(n + NTILE - 1) / NTILE, NNT, NODE_SMEM>>>(
        x, Wself, bself, Wagg, bagg, ln2g, ln2b, Wf1, bf1, Wf2, bf2, out, n);
}

// round 7
// speedup vs baseline: 3.9461x; 1.8065x over previous
#include <cuda_runtime.h>
#include <math.h>
#include <stdint.h>

#define HDIM 128
#define MAXN 50000

typedef unsigned long long ull;

// ---------------- device scratch ----------------
__device__ float g_h[(size_t)MAXN * HDIM];
__device__ float g_agg[(size_t)MAXN * HDIM];
__device__ float g_deg[MAXN];
// P = h @ [Wg1a | Wg1b | Wm1a | Wself]  -> [N, 512]
__device__ float g_P[(size_t)MAXN * 512];
// pair-interleaved tf32 weights for mma: G[(ks*4+t)*NW + n] = (W[ks*8+t][n], W[ks*8+t+4][n])
__device__ uint2 g_WP[32768];   // K=128, NW=512  (pcomp)
__device__ uint2 g_WE[16384];   // gate-e(4096) | msg1-e(4096) | msg2(8192), NW=128

// ---------------- helpers ----------------
__device__ __forceinline__ float gelu_f(float x) {
    return 0.5f * x * (1.0f + erff(x * 0.70710678118654752f));
}
__device__ __forceinline__ float rtf(float v) {
    uint32_t u; asm("cvt.rna.tf32.f32 %0, %1;" : "=r"(u) : "f"(v));
    return __uint_as_float(u);
}
__device__ __forceinline__ uint32_t rtfu(float v) {
    uint32_t u; asm("cvt.rna.tf32.f32 %0, %1;" : "=r"(u) : "f"(v));
    return u;
}
__device__ __forceinline__ ull pack2(float v) {
    ull r; asm("mov.b64 %0, {%1, %1};" : "=l"(r) : "f"(v)); return r;
}
__device__ __forceinline__ void fma2(ull& c, ull a, ull b) {
    asm("fma.rn.f32x2 %0, %1, %2, %0;" : "+l"(c) : "l"(a), "l"(b));
}
__device__ __forceinline__ float2 unpack2(ull v) {
    float2 f; asm("mov.b64 {%0, %1}, %2;" : "=f"(f.x), "=f"(f.y) : "l"(v)); return f;
}
__device__ __forceinline__ void mma8(float* d, const uint32_t* a, const uint32_t* b) {
    asm volatile("mma.sync.aligned.m16n8k8.row.col.f32.tf32.tf32.f32 "
                 "{%0,%1,%2,%3}, {%4,%5,%6,%7}, {%8,%9}, {%0,%1,%2,%3};"
                 : "+f"(d[0]), "+f"(d[1]), "+f"(d[2]), "+f"(d[3])
                 : "r"(a[0]), "r"(a[1]), "r"(a[2]), "r"(a[3]), "r"(b[0]), "r"(b[1]));
}
__device__ __forceinline__ void red2(float* p, float a, float b) {
    asm volatile("red.global.add.v2.f32 [%0], {%1, %2};" :: "l"(p), "f"(a), "f"(b) : "memory");
}
__device__ __forceinline__ void zeroD(float D[2][8][4]) {
#pragma unroll
    for (int mt = 0; mt < 2; ++mt)
#pragma unroll
        for (int nt = 0; nt < 8; ++nt)
#pragma unroll
            for (int j = 0; j < 4; ++j) D[mt][nt][j] = 0.0f;
}

// Warp GEMM: D[32x64] += As[rbase..+31][acol0..+8*ks) @ W2 (pair-interleaved tf32).
// wcol = global column base for this warp; D col c = wcol + nt*8 + t*2.
template<int LDA, int NW>
__device__ __forceinline__ void wgemm2(float D[2][8][4], const float* As, int acol0, int ksteps,
                                       const uint2* W2, int wcol, int rbase, int g, int t) {
    const float* Ap = As + (rbase + g) * LDA + acol0 + t;
    const uint2* Wp = W2 + (size_t)t * NW + wcol + g;
#pragma unroll 4
    for (int ks = 0; ks < ksteps; ++ks) {
        uint32_t a[2][4];
        uint2 b[8];
        int ao = ks * 8;
#pragma unroll
        for (int mt = 0; mt < 2; ++mt) {
            const float* Am = Ap + mt * 16 * LDA;
            a[mt][0] = __float_as_uint(Am[ao]);
            a[mt][1] = __float_as_uint(Am[8 * LDA + ao]);
            a[mt][2] = __float_as_uint(Am[ao + 4]);
            a[mt][3] = __float_as_uint(Am[8 * LDA + ao + 4]);
        }
        const uint2* Wk = Wp + (size_t)ks * 4 * NW;
#pragma unroll
        for (int nt = 0; nt < 8; ++nt) b[nt] = __ldg(Wk + nt * 8);
#pragma unroll
        for (int mt = 0; mt < 2; ++mt)
#pragma unroll
            for (int nt = 0; nt < 8; ++nt)
                mma8(D[mt][nt], a[mt], (const uint32_t*)&b[nt]);
    }
}

// ---------------- Kernel 0: build pair-interleaved tf32 weights ----------------
__global__ void prep_wt_kernel(const float* __restrict__ Wg1, const float* __restrict__ Wm1,
                               const float* __restrict__ Wm2, const float* __restrict__ Wself) {
    int idx = blockIdx.x * 256 + threadIdx.x;
    if (idx >= 49152) return;
    if (idx < 32768) {   // g_WP: NW=512, K=128
        int ks = idx >> 11, t = (idx >> 9) & 3, n = idx & 511;
        int k = ks * 8 + t;
        float v0, v1;
        if (n < 128)      { v0 = Wg1[k * 128 + n];           v1 = Wg1[(k + 4) * 128 + n]; }
        else if (n < 256) { v0 = Wg1[(128 + k) * 128 + n - 128]; v1 = Wg1[(132 + k) * 128 + n - 128]; }
        else if (n < 384) { v0 = Wm1[k * 128 + n - 256];     v1 = Wm1[(k + 4) * 128 + n - 256]; }
        else              { v0 = Wself[k * 128 + n - 384];   v1 = Wself[(k + 4) * 128 + n - 384]; }
        g_WP[idx] = make_uint2(rtfu(v0), rtfu(v1));
    } else {             // g_WE: NW=128
        int j = idx - 32768;
        int seg = (j < 4096) ? 0 : (j < 8192 ? 1 : 2);
        int j2 = j - (seg == 0 ? 0 : (seg == 1 ? 4096 : 8192));
        int ks = j2 >> 9, t = (j2 >> 7) & 3, n = j2 & 127;
        int k = ks * 8 + t;
        float v0, v1;
        if (seg == 0)      { v0 = Wg1[(256 + k) * 128 + n]; v1 = Wg1[(260 + k) * 128 + n]; }
        else if (seg == 1) { v0 = Wm1[(128 + k) * 128 + n]; v1 = Wm1[(132 + k) * 128 + n]; }
        else               { v0 = Wm2[k * 128 + n];         v1 = Wm2[(k + 4) * 128 + n]; }
        g_WE[j] = make_uint2(rtfu(v0), rtfu(v1));
    }
}

// ---------------- Kernel 1: LN(x) -> g_h, zero agg/deg ----------------
__global__ void ln1_zero_kernel(const float* __restrict__ x,
                                const float* __restrict__ g, const float* __restrict__ b, int n) {
    int row = blockIdx.x * 8 + (threadIdx.x >> 5);
    int lane = threadIdx.x & 31;
    if (row >= n) return;
    float4 v = ((const float4*)(x + (size_t)row * HDIM))[lane];
    float s = v.x + v.y + v.z + v.w;
#pragma unroll
    for (int o = 16; o; o >>= 1) s += __shfl_xor_sync(0xffffffffu, s, o);
    float m = s * (1.0f / 128.0f);
    float dx = v.x - m, dy = v.y - m, dz = v.z - m, dw = v.w - m;
    float q = dx * dx + dy * dy + dz * dz + dw * dw;
#pragma unroll
    for (int o = 16; o; o >>= 1) q += __shfl_xor_sync(0xffffffffu, q, o);
    float rstd = rsqrtf(q * (1.0f / 128.0f) + 1e-5f);
    float4 gv = ((const float4*)g)[lane];
    float4 bv = ((const float4*)b)[lane];
    float4 h;
    h.x = dx * rstd * gv.x + bv.x;
    h.y = dy * rstd * gv.y + bv.y;
    h.z = dz * rstd * gv.z + bv.z;
    h.w = dw * rstd * gv.w + bv.w;
    ((float4*)(g_h + (size_t)row * HDIM))[lane] = h;
    ((float4*)(g_agg + (size_t)row * HDIM))[lane] = make_float4(0.f, 0.f, 0.f, 0.f);
    if (lane == 0) g_deg[row] = 0.0f;
}

// ---------------- Kernel 2: P = h @ [Wg1a|Wg1b|Wm1a|Wself] ----------------
#define PLDA 132
__global__ __launch_bounds__(256, 2) void pcomp_kernel(int n) {
    extern __shared__ float As[];   // 128 x 132
    int tid = threadIdx.x, lane = tid & 31, wid = tid >> 5;
    int g = lane >> 2, t = lane & 3;
    int rbase = (wid >> 1) * 32, cbase = (wid & 1) * 64;
    int n0 = blockIdx.x * 128;
    int wcol = blockIdx.y * 128 + cbase;

    for (int idx = tid; idx < 128 * 32; idx += 256) {
        int r = idx >> 5, q = idx & 31;
        int nn = n0 + r; if (nn >= n) nn = n - 1;
        float4 v = ((const float4*)(g_h + (size_t)nn * HDIM))[q];
        float* dst = As + r * PLDA + q * 4;
        dst[0] = rtf(v.x); dst[1] = rtf(v.y); dst[2] = rtf(v.z); dst[3] = rtf(v.w);
    }
    __syncthreads();

    float D[2][8][4];
    zeroD(D);
    wgemm2<PLDA, 512>(D, As, 0, 16, g_WP, wcol, rbase, g, t);

#pragma unroll
    for (int mt = 0; mt < 2; ++mt) {
        int r0 = rbase + mt * 16 + g;
        int rr0 = n0 + r0, rr1 = rr0 + 8;
#pragma unroll
        for (int nt = 0; nt < 8; ++nt) {
            int c = wcol + nt * 8 + t * 2;
            if (rr0 < n) *(float2*)(g_P + (size_t)rr0 * 512 + c) = make_float2(D[mt][nt][0], D[mt][nt][1]);
            if (rr1 < n) *(float2*)(g_P + (size_t)rr1 * 512 + c) = make_float2(D[mt][nt][2], D[mt][nt][3]);
        }
    }
}

// ---------------- Kernel 3: edge MLPs (e-only GEMMs + P epilogues) ----------------
#define ELDA 196
__global__ __launch_bounds__(256, 2) void edge_kernel(
    const int* __restrict__ esrc, const int* __restrict__ edst,
    const float* __restrict__ eemb,
    const float* __restrict__ bg1, const float* __restrict__ Wg2, const float* __restrict__ bg2,
    const float* __restrict__ bm1, const float* __restrict__ bm2,
    float* __restrict__ out_edge, int E_) {
    extern __shared__ float sm[];
    float* As = sm;                   // 128 x 196: cols 0-63 e, 64-191 Z
    float* gs = sm + 128 * ELDA;      // 128
    int* esm = (int*)(gs + 128);
    int* edm = esm + 128;

    int tid = threadIdx.x, lane = tid & 31, wid = tid >> 5;
    int g = lane >> 2, t = lane & 3;
    int rbase = (wid >> 1) * 32, cbase = (wid & 1) * 64;
    long long e0 = (long long)blockIdx.x * 128;

    if (tid < 128) {
        long long eg = e0 + tid;
        int cl = (eg < E_) ? (int)eg : (E_ - 1);
        int s = esrc[cl], d = edst[cl];
        esm[tid] = s; edm[tid] = d; gs[tid] = 0.0f;
        if (eg < E_) atomicAdd(&g_deg[d], 1.0f);
    }
    __syncthreads();

    // gather e (64 floats/edge), tf32-rounded
    for (int idx = tid; idx < 128 * 16; idx += 256) {
        int r = idx >> 4, q = idx & 15;
        long long eg = e0 + r; if (eg >= E_) eg = E_ - 1;
        float4 v = ((const float4*)(eemb + eg * 64))[q];
        float* dst = As + r * ELDA + q * 4;
        dst[0] = rtf(v.x); dst[1] = rtf(v.y); dst[2] = rtf(v.z); dst[3] = rtf(v.w);
    }
    __syncthreads();

    float D[2][8][4];

    // ---- gate e-part: e @ Wg1[256:320]; epilogue adds P[dst][c] + P[src][128+c] ----
    zeroD(D);
    wgemm2<ELDA, 128>(D, As, 0, 8, g_WE, cbase, rbase, g, t);
#pragma unroll
    for (int mt = 0; mt < 2; ++mt) {
        int r0 = rbase + mt * 16 + g, r1 = r0 + 8;
        const float* P0d = g_P + (size_t)edm[r0] * 512;
        const float* P0s = g_P + (size_t)esm[r0] * 512;
        const float* P1d = g_P + (size_t)edm[r1] * 512;
        const float* P1s = g_P + (size_t)esm[r1] * 512;
        float s0 = 0.f, s1 = 0.f;
#pragma unroll
        for (int nt = 0; nt < 8; ++nt) {
            int c = cbase + nt * 8 + t * 2;
            float2 pd0 = *(const float2*)(P0d + c);
            float2 ps0 = *(const float2*)(P0s + 128 + c);
            float2 pd1 = *(const float2*)(P1d + c);
            float2 ps1 = *(const float2*)(P1s + 128 + c);
            float b0 = __ldg(bg1 + c), b1 = __ldg(bg1 + c + 1);
            float w0 = __ldg(Wg2 + c), w1 = __ldg(Wg2 + c + 1);
            s0 += gelu_f(D[mt][nt][0] + pd0.x + ps0.x + b0) * w0
                + gelu_f(D[mt][nt][1] + pd0.y + ps0.y + b1) * w1;
            s1 += gelu_f(D[mt][nt][2] + pd1.x + ps1.x + b0) * w0
                + gelu_f(D[mt][nt][3] + pd1.y + ps1.y + b1) * w1;
        }
        s0 += __shfl_xor_sync(0xffffffffu, s0, 1); s0 += __shfl_xor_sync(0xffffffffu, s0, 2);
        s1 += __shfl_xor_sync(0xffffffffu, s1, 1); s1 += __shfl_xor_sync(0xffffffffu, s1, 2);
        if (t == 0) { atomicAdd(&gs[r0], s0); atomicAdd(&gs[r1], s1); }
    }

    // ---- msg1 e-part: e @ Wm1[128:192]; Z = gelu(D + P[src][256+c] + bm1) ----
    zeroD(D);
    wgemm2<ELDA, 128>(D, As, 0, 8, g_WE + 4096, cbase, rbase, g, t);
#pragma unroll
    for (int mt = 0; mt < 2; ++mt) {
        int r0 = rbase + mt * 16 + g, r1 = r0 + 8;
        const float* P0 = g_P + (size_t)esm[r0] * 512 + 256;
        const float* P1 = g_P + (size_t)esm[r1] * 512 + 256;
#pragma unroll
        for (int nt = 0; nt < 8; ++nt) {
            int c = cbase + nt * 8 + t * 2;
            float2 pm0 = *(const float2*)(P0 + c);
            float2 pm1 = *(const float2*)(P1 + c);
            float b0 = __ldg(bm1 + c), b1 = __ldg(bm1 + c + 1);
            *(float2*)(As + r0 * ELDA + 64 + c) =
                make_float2(rtf(gelu_f(D[mt][nt][0] + pm0.x + b0)),
                            rtf(gelu_f(D[mt][nt][1] + pm0.y + b1)));
            *(float2*)(As + r1 * ELDA + 64 + c) =
                make_float2(rtf(gelu_f(D[mt][nt][2] + pm1.x + b0)),
                            rtf(gelu_f(D[mt][nt][3] + pm1.y + b1)));
        }
    }
    __syncthreads();

    // ---- msg2: Z @ Wm2 ----
    zeroD(D);
    wgemm2<ELDA, 128>(D, As, 64, 16, g_WE + 8192, cbase, rbase, g, t);

    // ---- final: edge_repr = (D + bm2) * sigmoid(gs); red.v2 scatter ----
    float bg2v = __ldg(bg2);
#pragma unroll
    for (int mt = 0; mt < 2; ++mt) {
        int r0 = rbase + mt * 16 + g, r1 = r0 + 8;
        float gt0 = 1.0f / (1.0f + expf(-(gs[r0] + bg2v)));
        float gt1 = 1.0f / (1.0f + expf(-(gs[r1] + bg2v)));
        long long eg0 = e0 + r0, eg1 = e0 + r1;
        int d0 = edm[r0], d1 = edm[r1];
#pragma unroll
        for (int nt = 0; nt < 8; ++nt) {
            int c = cbase + nt * 8 + t * 2;
            float b0 = __ldg(bm2 + c), b1 = __ldg(bm2 + c + 1);
            if (eg0 < E_) {
                float v0 = (D[mt][nt][0] + b0) * gt0, v1 = (D[mt][nt][1] + b1) * gt0;
                *(float2*)(out_edge + eg0 * 128 + c) = make_float2(v0, v1);
                red2(g_agg + (size_t)d0 * 128 + c, v0, v1);
            }
            if (eg1 < E_) {
                float v2 = (D[mt][nt][2] + b0) * gt1, v3 = (D[mt][nt][3] + b1) * gt1;
                *(float2*)(out_edge + eg1 * 128 + c) = make_float2(v2, v3);
                red2(g_agg + (size_t)d1 * 128 + c, v2, v3);
            }
        }
    }
}

// ---------------- scalar GEMM core (f32x2) ----------------
template<int K, int LDA, int LDW>
__device__ __forceinline__ void gemm_acc(ull c2[8][4], const float* __restrict__ As,
                                         const float* __restrict__ W, int tr, int tc) {
    const float* Ab = As + tr * 8 * LDA;
    const float* Wb = W + tc * 8;
#pragma unroll 4
    for (int k = 0; k < K; k++) {
        const ull* wp = (const ull*)(Wb + (size_t)k * LDW);
        ull w0 = __ldg(wp + 0), w1 = __ldg(wp + 1), w2 = __ldg(wp + 2), w3 = __ldg(wp + 3);
#pragma unroll
        for (int i = 0; i < 8; i++) {
            ull a2 = pack2(Ab[i * LDA + k]);
            fma2(c2[i][0], a2, w0); fma2(c2[i][1], a2, w1);
            fma2(c2[i][2], a2, w2); fma2(c2[i][3], a2, w3);
        }
    }
}
__device__ __forceinline__ void zero_acc(ull c2[8][4]) {
#pragma unroll
    for (int i = 0; i < 8; i++)
#pragma unroll
        for (int p = 0; p < 4; p++) c2[i][p] = 0ull;
}

// ---------------- Kernel 4: node update + FFN ----------------
#define NTILE 64
#define NNT   128
__global__ __launch_bounds__(NNT, 2) void node_kernel(
    const float* __restrict__ x,
    const float* __restrict__ bself,
    const float* __restrict__ Wagg,  const float* __restrict__ bagg,
    const float* __restrict__ ln2g,  const float* __restrict__ ln2b,
    const float* __restrict__ Wf1,   const float* __restrict__ bf1,
    const float* __restrict__ Wf2,   const float* __restrict__ bf2,
    float* __restrict__ out, int n) {
    extern __shared__ float sm[];
    float* AG  = sm;                    // 64x128 (agg, later T-half)
    float* OUT = AG + NTILE * 128;      // 64x128
    float* TH  = OUT + NTILE * 128;     // 64x128 (ln2 out)
    float* muv = TH + NTILE * 128;
    float* rsv = muv + NTILE;

    int tid = threadIdx.x;
    int tc = tid & 15, tr = tid >> 4;
    int n0 = blockIdx.x * NTILE;

    for (int idx = tid; idx < NTILE * 32; idx += NNT) {
        int r = idx >> 5, q = idx & 31;
        int nn = n0 + r; if (nn >= n) nn = n - 1;
        float4 a = ((const float4*)(g_agg + (size_t)nn * HDIM))[q];
        float inv = 1.0f / fmaxf(g_deg[nn], 1.0f);
        a.x *= inv; a.y *= inv; a.z *= inv; a.w *= inv;
        ((float4*)(AG + r * 128))[q] = a;
    }
    __syncthreads();

    ull c2[8][4];
    zero_acc(c2);
    gemm_acc<128, 128, 128>(c2, AG, Wagg, tr, tc);
    {
        float b[8];
#pragma unroll
        for (int j = 0; j < 8; j++) b[j] = __ldg(bself + tc * 8 + j) + __ldg(bagg + tc * 8 + j);
#pragma unroll
        for (int i = 0; i < 8; i++) {
            int r = tr * 8 + i;
            int nn = n0 + r; if (nn >= n) nn = n - 1;
            float4 x0 = __ldg((const float4*)(x + (size_t)nn * HDIM + tc * 8));
            float4 x1 = __ldg((const float4*)(x + (size_t)nn * HDIM + tc * 8 + 4));
            float4 p0 = __ldg((const float4*)(g_P + (size_t)nn * 512 + 384 + tc * 8));
            float4 p1 = __ldg((const float4*)(g_P + (size_t)nn * 512 + 384 + tc * 8 + 4));
            float v[8];
#pragma unroll
            for (int p = 0; p < 4; p++) { float2 f = unpack2(c2[i][p]); v[2*p] = f.x; v[2*p+1] = f.y; }
            *(float4*)(OUT + r * 128 + tc * 8) =
                make_float4(v[0]+b[0]+x0.x+p0.x, v[1]+b[1]+x0.y+p0.y, v[2]+b[2]+x0.z+p0.z, v[3]+b[3]+x0.w+p0.w);
            *(float4*)(OUT + r * 128 + tc * 8 + 4) =
                make_float4(v[4]+b[4]+x1.x+p1.x, v[5]+b[5]+x1.y+p1.y, v[6]+b[6]+x1.z+p1.z, v[7]+b[7]+x1.w+p1.w);
        }
    }
    __syncthreads();

    {   // LN2 stats
        int w = tid >> 5, lane = tid & 31;
        for (int r = w; r < NTILE; r += 4) {
            const float* o = OUT + r * 128;
            float v0 = o[lane], v1 = o[lane + 32], v2 = o[lane + 64], v3 = o[lane + 96];
            float s = v0 + v1 + v2 + v3;
#pragma unroll
            for (int of = 16; of; of >>= 1) s += __shfl_xor_sync(0xffffffffu, s, of);
            float m = s * (1.0f / 128.0f);
            float d0 = v0 - m, d1 = v1 - m, d2 = v2 - m, d3 = v3 - m;
            float q = d0*d0 + d1*d1 + d2*d2 + d3*d3;
#pragma unroll
            for (int of = 16; of; of >>= 1) q += __shfl_xor_sync(0xffffffffu, q, of);
            if (lane == 0) { muv[r] = m; rsv[r] = rsqrtf(q * (1.0f / 128.0f) + 1e-5f); }
        }
    }
    __syncthreads();
    for (int idx = tid; idx < NTILE * 128; idx += NNT) {
        int r = idx >> 7, c = idx & 127;
        TH[idx] = (OUT[idx] - muv[r]) * rsv[r] * __ldg(ln2g + c) + __ldg(ln2b + c);
    }
    __syncthreads();

    ull cf[8][4];
    zero_acc(cf);
#pragma unroll 1
    for (int half = 0; half < 2; half++) {
        zero_acc(c2);
        gemm_acc<128, 128, 256>(c2, TH, Wf1 + half * 128, tr, tc);
        if (half) __syncthreads();     // prior cf-gemm reads of AG complete
        float b[8];
#pragma unroll
        for (int j = 0; j < 8; j++) b[j] = __ldg(bf1 + half * 128 + tc * 8 + j);
#pragma unroll
        for (int i = 0; i < 8; i++) {
            int r = tr * 8 + i;
            float v[8];
#pragma unroll
            for (int p = 0; p < 4; p++) { float2 f = unpack2(c2[i][p]); v[2*p] = f.x; v[2*p+1] = f.y; }
            *(float4*)(AG + r * 128 + tc * 8) =
                make_float4(gelu_f(v[0]+b[0]), gelu_f(v[1]+b[1]), gelu_f(v[2]+b[2]), gelu_f(v[3]+b[3]));
            *(float4*)(AG + r * 128 + tc * 8 + 4) =
                make_float4(gelu_f(v[4]+b[4]), gelu_f(v[5]+b[5]), gelu_f(v[6]+b[6]), gelu_f(v[7]+b[7]));
        }
        __syncthreads();
        gemm_acc<128, 128, 128>(cf, AG, Wf2 + half * 128 * 128, tr, tc);
    }

    {
        float b[8];
#pragma unroll
        for (int j = 0; j < 8; j++) b[j] = __ldg(bf2 + tc * 8 + j);
#pragma unroll
        for (int i = 0; i < 8; i++) {
            int r = tr * 8 + i;
            int nn = n0 + r;
            if (nn < n) {
                float v[8];
#pragma unroll
                for (int p = 0; p < 4; p++) { float2 f = unpack2(cf[i][p]); v[2*p] = f.x; v[2*p+1] = f.y; }
#pragma unroll
                for (int j = 0; j < 8; j++) v[j] = v[j] + b[j] + OUT[r * 128 + tc * 8 + j];
                *(float4*)(out + (size_t)nn * HDIM + tc * 8)     = make_float4(v[0], v[1], v[2], v[3]);
                *(float4*)(out + (size_t)nn * HDIM + tc * 8 + 4) = make_float4(v[4], v[5], v[6], v[7]);
            }
        }
    }
}

// ---------------- launch ----------------
extern "C" void kernel_launch(void* const* d_in, const int* in_sizes, int n_in,
                              void* d_out, int out_size) {
    const float* x     = (const float*)d_in[0];
    const int*   esrc  = (const int*)d_in[1];
    const int*   edst  = (const int*)d_in[2];
    const float* eemb  = (const float*)d_in[3];
    const float* ln1g  = (const float*)d_in[4];
    const float* ln1b  = (const float*)d_in[5];
    const float* Wself = (const float*)d_in[6];
    const float* bself = (const float*)d_in[7];
    const float* Wm1   = (const float*)d_in[8];
    const float* bm1   = (const float*)d_in[9];
    const float* Wm2   = (const float*)d_in[10];
    const float* bm2   = (const float*)d_in[11];
    const float* Wg1   = (const float*)d_in[12];
    const float* bg1   = (const float*)d_in[13];
    const float* Wg2   = (const float*)d_in[14];
    const float* bg2   = (const float*)d_in[15];
    const float* Wagg  = (const float*)d_in[16];
    const float* bagg  = (const float*)d_in[17];
    const float* ln2g  = (const float*)d_in[18];
    const float* ln2b  = (const float*)d_in[19];
    const float* Wf1   = (const float*)d_in[20];
    const float* bf1   = (const float*)d_in[21];
    const float* Wf2   = (const float*)d_in[22];
    const float* bf2   = (const float*)d_in[23];

    int n = in_sizes[0] / HDIM;
    int E = in_sizes[1];
    float* out      = (float*)d_out;
    float* out_edge = out + (size_t)n * HDIM;

    const int PC_SMEM   = 128 * PLDA * 4;
    const int EDGE_SMEM = (128 * ELDA + 128) * 4 + 128 * 4 * 2;
    const int NODE_SMEM = (NTILE * 128 * 3 + 2 * NTILE) * 4;
    cudaFuncSetAttribute(pcomp_kernel, cudaFuncAttributeMaxDynamicSharedMemorySize, PC_SMEM);
    cudaFuncSetAttribute(edge_kernel,  cudaFuncAttributeMaxDynamicSharedMemorySize, EDGE_SMEM);
    cudaFuncSetAttribute(node_kernel,  cudaFuncAttributeMaxDynamicSharedMemorySize, NODE_SMEM);

    prep_wt_kernel<<<(49152 + 255) / 256, 256>>>(Wg1, Wm1, Wm2, Wself);
    ln1_zero_kernel<<<(n + 7) / 8, 256>>>(x, ln1g, ln1b, n);
    dim3 pg((n + 127) / 128, 4);
    pcomp_kernel<<<pg, 256, PC_SMEM>>>(n);
    edge_kernel<<<(E + 127) / 128, 256, EDGE_SMEM>>>(
        esrc, edst, eemb, bg1, Wg2, bg2, bm1, bm2, out_edge, E);
    node_kernel<<<(n + NTILE - 1) / NTILE, NNT, NODE_SMEM>>>(
        x, bself, Wagg, bagg, ln2g, ln2b, Wf1, bf1, Wf2, bf2, out, n);
}

// round 11
// speedup vs baseline: 4.2294x; 1.0718x over previous
#include <cuda_runtime.h>
#include <math.h>
#include <stdint.h>

#define HDIM 128
#define MAXN 50000

// ---------------- device scratch ----------------
__device__ float g_h[(size_t)MAXN * HDIM];
__device__ float g_agg[(size_t)MAXN * HDIM];
__device__ float g_deg[MAXN];
// P = h @ [Wg1a | Wg1b | Wm1a | Wself]  -> [N, 512]
__device__ float g_P[(size_t)MAXN * 512];
// pair-interleaved tf32 weights: G[(ks*4+t)*NW + n] = (W[ks*8+t][n], W[ks*8+t+4][n])
__device__ uint2 g_WP[32768];   // pcomp: K=128, NW=512
__device__ uint2 g_WE[16384];   // gate-e(4096) | msg1-e(4096) | msg2(8192), NW=128
__device__ uint2 g_WN[40960];   // Wagg(8192) | Wf1(16384, NW=256) | Wf2(16384, K=256)
#define WAGG 0
#define WF1  8192
#define WF2  24576

// ---------------- helpers ----------------
__device__ __forceinline__ float gelu_f(float x) {
    return 0.5f * x * (1.0f + erff(x * 0.70710678118654752f));
}
__device__ __forceinline__ float rtf(float v) {
    uint32_t u; asm("cvt.rna.tf32.f32 %0, %1;" : "=r"(u) : "f"(v));
    return __uint_as_float(u);
}
__device__ __forceinline__ uint32_t rtfu(float v) {
    uint32_t u; asm("cvt.rna.tf32.f32 %0, %1;" : "=r"(u) : "f"(v));
    return u;
}
__device__ __forceinline__ void mma8(float* d, const uint32_t* a, const uint32_t* b) {
    asm volatile("mma.sync.aligned.m16n8k8.row.col.f32.tf32.tf32.f32 "
                 "{%0,%1,%2,%3}, {%4,%5,%6,%7}, {%8,%9}, {%0,%1,%2,%3};"
                 : "+f"(d[0]), "+f"(d[1]), "+f"(d[2]), "+f"(d[3])
                 : "r"(a[0]), "r"(a[1]), "r"(a[2]), "r"(a[3]), "r"(b[0]), "r"(b[1]));
}
__device__ __forceinline__ void red2(float* p, float a, float b) {
    asm volatile("red.global.add.v2.f32 [%0], {%1, %2};" :: "l"(p), "f"(a), "f"(b) : "memory");
}
__device__ __forceinline__ void zeroD(float D[2][8][4]) {
#pragma unroll
    for (int mt = 0; mt < 2; ++mt)
#pragma unroll
        for (int nt = 0; nt < 8; ++nt)
#pragma unroll
            for (int j = 0; j < 4; ++j) D[mt][nt][j] = 0.0f;
}
__device__ __forceinline__ void zeroD4(float D[2][4][4]) {
#pragma unroll
    for (int mt = 0; mt < 2; ++mt)
#pragma unroll
        for (int nt = 0; nt < 4; ++nt)
#pragma unroll
            for (int j = 0; j < 4; ++j) D[mt][nt][j] = 0.0f;
}

// Warp GEMM 32x64: D += As[rbase..+31][acol0..+8*ks) @ W2 (pair-interleaved tf32).
template<int LDA, int NW>
__device__ __forceinline__ void wgemm2(float D[2][8][4], const float* As, int acol0, int ksteps,
                                       const uint2* W2, int wcol, int rbase, int g, int t) {
    const float* Ap = As + (rbase + g) * LDA + acol0 + t;
    const uint2* Wp = W2 + (size_t)t * NW + wcol + g;
#pragma unroll 4
    for (int ks = 0; ks < ksteps; ++ks) {
        uint32_t a[2][4];
        uint2 b[8];
        int ao = ks * 8;
#pragma unroll
        for (int mt = 0; mt < 2; ++mt) {
            const float* Am = Ap + mt * 16 * LDA;
            a[mt][0] = __float_as_uint(Am[ao]);
            a[mt][1] = __float_as_uint(Am[8 * LDA + ao]);
            a[mt][2] = __float_as_uint(Am[ao + 4]);
            a[mt][3] = __float_as_uint(Am[8 * LDA + ao + 4]);
        }
        const uint2* Wk = Wp + (size_t)ks * 4 * NW;
#pragma unroll
        for (int nt = 0; nt < 8; ++nt) b[nt] = __ldg(Wk + nt * 8);
#pragma unroll
        for (int mt = 0; mt < 2; ++mt)
#pragma unroll
            for (int nt = 0; nt < 8; ++nt)
                mma8(D[mt][nt], a[mt], (const uint32_t*)&b[nt]);
    }
}

// Warp GEMM 32x32 (4 col frags)
template<int LDA, int NW>
__device__ __forceinline__ void wgemm2n(float D[2][4][4], const float* As, int ksteps,
                                        const uint2* W2, int wcol, int rbase, int g, int t) {
    const float* Ap = As + (rbase + g) * LDA + t;
    const uint2* Wp = W2 + (size_t)t * NW + wcol + g;
#pragma unroll 4
    for (int ks = 0; ks < ksteps; ++ks) {
        uint32_t a[2][4];
        uint2 b[4];
        int ao = ks * 8;
#pragma unroll
        for (int mt = 0; mt < 2; ++mt) {
            const float* Am = Ap + mt * 16 * LDA;
            a[mt][0] = __float_as_uint(Am[ao]);
            a[mt][1] = __float_as_uint(Am[8 * LDA + ao]);
            a[mt][2] = __float_as_uint(Am[ao + 4]);
            a[mt][3] = __float_as_uint(Am[8 * LDA + ao + 4]);
        }
        const uint2* Wk = Wp + (size_t)ks * 4 * NW;
#pragma unroll
        for (int nt = 0; nt < 4; ++nt) b[nt] = __ldg(Wk + nt * 8);
#pragma unroll
        for (int mt = 0; mt < 2; ++mt)
#pragma unroll
            for (int nt = 0; nt < 4; ++nt)
                mma8(D[mt][nt], a[mt], (const uint32_t*)&b[nt]);
    }
}

#define DSL 132
// stage 32x64 fragments into DS[.][DSL]
__device__ __forceinline__ void storeD(float D[2][8][4], float* DS,
                                       int rbase, int cbase, int g, int t) {
#pragma unroll
    for (int mt = 0; mt < 2; ++mt) {
        int r0 = rbase + mt * 16 + g, r1 = r0 + 8;
#pragma unroll
        for (int nt = 0; nt < 8; ++nt) {
            int c = cbase + nt * 8 + t * 2;
            *(float2*)(DS + r0 * DSL + c) = make_float2(D[mt][nt][0], D[mt][nt][1]);
            *(float2*)(DS + r1 * DSL + c) = make_float2(D[mt][nt][2], D[mt][nt][3]);
        }
    }
}
// stage 32x32 fragments into DS[.][DSL]
__device__ __forceinline__ void storeD4(float D[2][4][4], float* DS,
                                        int rbase, int cbase, int g, int t) {
#pragma unroll
    for (int mt = 0; mt < 2; ++mt) {
        int r0 = rbase + mt * 16 + g, r1 = r0 + 8;
#pragma unroll
        for (int nt = 0; nt < 4; ++nt) {
            int c = cbase + nt * 8 + t * 2;
            *(float2*)(DS + r0 * DSL + c) = make_float2(D[mt][nt][0], D[mt][nt][1]);
            *(float2*)(DS + r1 * DSL + c) = make_float2(D[mt][nt][2], D[mt][nt][3]);
        }
    }
}

// ---------------- Kernel 0a: pcomp/edge weights ----------------
__global__ void prep_wt_kernel(const float* __restrict__ Wg1, const float* __restrict__ Wm1,
                               const float* __restrict__ Wm2, const float* __restrict__ Wself) {
    int idx = blockIdx.x * 256 + threadIdx.x;
    if (idx >= 49152) return;
    if (idx < 32768) {   // g_WP: NW=512, K=128
        int ks = idx >> 11, t = (idx >> 9) & 3, n = idx & 511;
        int k = ks * 8 + t;
        float v0, v1;
        if (n < 128)      { v0 = Wg1[k * 128 + n];           v1 = Wg1[(k + 4) * 128 + n]; }
        else if (n < 256) { v0 = Wg1[(128 + k) * 128 + n - 128]; v1 = Wg1[(132 + k) * 128 + n - 128]; }
        else if (n < 384) { v0 = Wm1[k * 128 + n - 256];     v1 = Wm1[(k + 4) * 128 + n - 256]; }
        else              { v0 = Wself[k * 128 + n - 384];   v1 = Wself[(k + 4) * 128 + n - 384]; }
        g_WP[idx] = make_uint2(rtfu(v0), rtfu(v1));
    } else {             // g_WE: NW=128
        int j = idx - 32768;
        int seg = (j < 4096) ? 0 : (j < 8192 ? 1 : 2);
        int j2 = j - (seg == 0 ? 0 : (seg == 1 ? 4096 : 8192));
        int ks = j2 >> 9, t = (j2 >> 7) & 3, n = j2 & 127;
        int k = ks * 8 + t;
        float v0, v1;
        if (seg == 0)      { v0 = Wg1[(256 + k) * 128 + n]; v1 = Wg1[(260 + k) * 128 + n]; }
        else if (seg == 1) { v0 = Wm1[(128 + k) * 128 + n]; v1 = Wm1[(132 + k) * 128 + n]; }
        else               { v0 = Wm2[k * 128 + n];         v1 = Wm2[(k + 4) * 128 + n]; }
        g_WE[j] = make_uint2(rtfu(v0), rtfu(v1));
    }
}

// ---------------- Kernel 0b: node weights ----------------
__global__ void prep_wt2_kernel(const float* __restrict__ Wagg,
                                const float* __restrict__ Wf1,
                                const float* __restrict__ Wf2) {
    int idx = blockIdx.x * 256 + threadIdx.x;
    if (idx >= 40960) return;
    float v0, v1;
    if (idx < 8192) {           // Wagg [128,128], NW=128
        int ks = idx >> 9, t = (idx >> 7) & 3, n = idx & 127;
        int k = ks * 8 + t;
        v0 = Wagg[k * 128 + n]; v1 = Wagg[(k + 4) * 128 + n];
        g_WN[idx] = make_uint2(rtfu(v0), rtfu(v1));
    } else if (idx < 24576) {   // Wf1 [128,256], NW=256
        int j = idx - 8192;
        int ks = j >> 10, t = (j >> 8) & 3, n = j & 255;
        int k = ks * 8 + t;
        v0 = Wf1[k * 256 + n]; v1 = Wf1[(k + 4) * 256 + n];
        g_WN[idx] = make_uint2(rtfu(v0), rtfu(v1));
    } else {                    // Wf2 [256,128], NW=128, K=256 (ks 0-31)
        int j = idx - 24576;
        int ks = j >> 9, t = (j >> 7) & 3, n = j & 127;
        int k = ks * 8 + t;
        v0 = Wf2[k * 128 + n]; v1 = Wf2[(k + 4) * 128 + n];
        g_WN[idx] = make_uint2(rtfu(v0), rtfu(v1));
    }
}

// ---------------- Kernel 1: LN(x) -> g_h, zero agg/deg ----------------
__global__ void ln1_zero_kernel(const float* __restrict__ x,
                                const float* __restrict__ g, const float* __restrict__ b, int n) {
    int row = blockIdx.x * 8 + (threadIdx.x >> 5);
    int lane = threadIdx.x & 31;
    if (row >= n) return;
    float4 v = ((const float4*)(x + (size_t)row * HDIM))[lane];
    float s = v.x + v.y + v.z + v.w;
#pragma unroll
    for (int o = 16; o; o >>= 1) s += __shfl_xor_sync(0xffffffffu, s, o);
    float m = s * (1.0f / 128.0f);
    float dx = v.x - m, dy = v.y - m, dz = v.z - m, dw = v.w - m;
    float q = dx * dx + dy * dy + dz * dz + dw * dw;
#pragma unroll
    for (int o = 16; o; o >>= 1) q += __shfl_xor_sync(0xffffffffu, q, o);
    float rstd = rsqrtf(q * (1.0f / 128.0f) + 1e-5f);
    float4 gv = ((const float4*)g)[lane];
    float4 bv = ((const float4*)b)[lane];
    float4 h;
    h.x = dx * rstd * gv.x + bv.x;
    h.y = dy * rstd * gv.y + bv.y;
    h.z = dz * rstd * gv.z + bv.z;
    h.w = dw * rstd * gv.w + bv.w;
    ((float4*)(g_h + (size_t)row * HDIM))[lane] = h;
    ((float4*)(g_agg + (size_t)row * HDIM))[lane] = make_float4(0.f, 0.f, 0.f, 0.f);
    if (lane == 0) g_deg[row] = 0.0f;
}

// ---------------- Kernel 2: P = h @ [Wg1a|Wg1b|Wm1a|Wself] ----------------
#define PLDA 132
__global__ __launch_bounds__(256, 2) void pcomp_kernel(int n) {
    extern __shared__ float As[];   // 128 x 132
    int tid = threadIdx.x, lane = tid & 31, wid = tid >> 5;
    int g = lane >> 2, t = lane & 3;
    int rbase = (wid >> 1) * 32, cbase = (wid & 1) * 64;
    int n0 = blockIdx.x * 128;
    int wcol = blockIdx.y * 128 + cbase;

    for (int idx = tid; idx < 128 * 32; idx += 256) {
        int r = idx >> 5, q = idx & 31;
        int nn = n0 + r; if (nn >= n) nn = n - 1;
        float4 v = ((const float4*)(g_h + (size_t)nn * HDIM))[q];
        float* dst = As + r * PLDA + q * 4;
        dst[0] = rtf(v.x); dst[1] = rtf(v.y); dst[2] = rtf(v.z); dst[3] = rtf(v.w);
    }
    __syncthreads();

    float D[2][8][4];
    zeroD(D);
    wgemm2<PLDA, 512>(D, As, 0, 16, g_WP, wcol, rbase, g, t);

#pragma unroll
    for (int mt = 0; mt < 2; ++mt) {
        int r0 = rbase + mt * 16 + g;
        int rr0 = n0 + r0, rr1 = rr0 + 8;
#pragma unroll
        for (int nt = 0; nt < 8; ++nt) {
            int c = wcol + nt * 8 + t * 2;
            if (rr0 < n) *(float2*)(g_P + (size_t)rr0 * 512 + c) = make_float2(D[mt][nt][0], D[mt][nt][1]);
            if (rr1 < n) *(float2*)(g_P + (size_t)rr1 * 512 + c) = make_float2(D[mt][nt][2], D[mt][nt][3]);
        }
    }
}

// ---------------- Kernel 3: edge MLPs, row-order epilogues via DS staging ----------------
#define EA 68
__global__ __launch_bounds__(256, 2) void edge_kernel(
    const int* __restrict__ esrc, const int* __restrict__ edst,
    const float* __restrict__ eemb,
    const float* __restrict__ bg1, const float* __restrict__ Wg2, const float* __restrict__ bg2,
    const float* __restrict__ bm1, const float* __restrict__ bm2,
    float* __restrict__ out_edge, int E_) {
    extern __shared__ float sm[];
    float* Ae = sm;                   // 128 x 68 (e, tf32)
    float* DS = sm + 128 * EA;        // 128 x 132 (staged D / Z)
    float* gs = DS + 128 * DSL;       // 128 gate pre-activations
    int* esm = (int*)(gs + 128);
    int* edm = esm + 128;

    int tid = threadIdx.x, lane = tid & 31, wid = tid >> 5;
    int g = lane >> 2, t = lane & 3;
    int rbase = (wid >> 1) * 32, cbase = (wid & 1) * 64;
    long long e0 = (long long)blockIdx.x * 128;

    if (tid < 128) {
        long long eg = e0 + tid;
        int cl = (eg < E_) ? (int)eg : (E_ - 1);
        int s = esrc[cl], d = edst[cl];
        esm[tid] = s; edm[tid] = d;
        if (eg < E_) atomicAdd(&g_deg[d], 1.0f);
    }
    __syncthreads();

    // gather e (64 floats/edge), tf32-rounded
    for (int idx = tid; idx < 128 * 16; idx += 256) {
        int r = idx >> 4, q = idx & 15;
        long long eg = e0 + r; if (eg >= E_) eg = E_ - 1;
        float4 v = ((const float4*)(eemb + eg * 64))[q];
        float* dst = Ae + r * EA + q * 4;
        dst[0] = rtf(v.x); dst[1] = rtf(v.y); dst[2] = rtf(v.z); dst[3] = rtf(v.w);
    }
    __syncthreads();

    float D[2][8][4];

    // ---- GEMM1: gate e-part -> DS ----
    zeroD(D);
    wgemm2<EA, 128>(D, Ae, 0, 8, g_WE, cbase, rbase, g, t);
    storeD(D, DS, rbase, cbase, g, t);
    __syncthreads();

    // ---- gate pass (warp per row, fully coalesced) ----
    for (int r = wid; r < 128; r += 8) {
        const float* Pd = g_P + (size_t)edm[r] * 512;
        const float* Ps = g_P + (size_t)esm[r] * 512 + 128;
        float4 de = *(const float4*)(DS + r * DSL + lane * 4);
        float4 pd = __ldg((const float4*)(Pd + lane * 4));
        float4 ps = __ldg((const float4*)(Ps + lane * 4));
        float4 bb = __ldg((const float4*)(bg1 + lane * 4));
        float4 ww = __ldg((const float4*)(Wg2 + lane * 4));
        float s = gelu_f(de.x + pd.x + ps.x + bb.x) * ww.x
                + gelu_f(de.y + pd.y + ps.y + bb.y) * ww.y
                + gelu_f(de.z + pd.z + ps.z + bb.z) * ww.z
                + gelu_f(de.w + pd.w + ps.w + bb.w) * ww.w;
#pragma unroll
        for (int o = 16; o; o >>= 1) s += __shfl_xor_sync(0xffffffffu, s, o);
        if (lane == 0) gs[r] = s;
    }
    __syncthreads();

    // ---- GEMM2: msg1 e-part -> DS ----
    zeroD(D);
    wgemm2<EA, 128>(D, Ae, 0, 8, g_WE + 4096, cbase, rbase, g, t);
    storeD(D, DS, rbase, cbase, g, t);
    __syncthreads();

    // ---- msg1 pass: Z = rtf(gelu(D + P[src][256:384] + bm1)) in-place ----
    for (int r = wid; r < 128; r += 8) {
        const float* Pm = g_P + (size_t)esm[r] * 512 + 256;
        float* row = DS + r * DSL + lane * 4;
        float4 d = *(const float4*)row;
        float4 pm = __ldg((const float4*)(Pm + lane * 4));
        float4 bb = __ldg((const float4*)(bm1 + lane * 4));
        *(float4*)row = make_float4(rtf(gelu_f(d.x + pm.x + bb.x)),
                                    rtf(gelu_f(d.y + pm.y + bb.y)),
                                    rtf(gelu_f(d.z + pm.z + bb.z)),
                                    rtf(gelu_f(d.w + pm.w + bb.w)));
    }
    __syncthreads();

    // ---- GEMM3: msg2 = Z @ Wm2 ----
    zeroD(D);
    wgemm2<DSL, 128>(D, DS, 0, 16, g_WE + 8192, cbase, rbase, g, t);
    __syncthreads();                 // all Z reads done
    storeD(D, DS, rbase, cbase, g, t);
    __syncthreads();

    // ---- final pass: edge_repr + scatter (coalesced) ----
    float bg2v = __ldg(bg2);
    for (int r = wid; r < 128; r += 8) {
        long long eg = e0 + r;
        if (eg >= E_) continue;
        float gt = 1.0f / (1.0f + expf(-(gs[r] + bg2v)));
        float4 d = *(const float4*)(DS + r * DSL + lane * 4);
        float4 bb = __ldg((const float4*)(bm2 + lane * 4));
        float4 v = make_float4((d.x + bb.x) * gt, (d.y + bb.y) * gt,
                               (d.z + bb.z) * gt, (d.w + bb.w) * gt);
        *(float4*)(out_edge + eg * 128 + lane * 4) = v;
        float* ap = g_agg + (size_t)edm[r] * 128 + lane * 4;
        red2(ap, v.x, v.y);
        red2(ap + 2, v.z, v.w);
    }
}

// ---------------- Kernel 4: node update + FFN (mma) ----------------
#define NR 64
__global__ __launch_bounds__(256, 2) void node_kernel(
    const float* __restrict__ x,
    const float* __restrict__ bself, const float* __restrict__ bagg,
    const float* __restrict__ ln2g,  const float* __restrict__ ln2b,
    const float* __restrict__ bf1,   const float* __restrict__ bf2,
    float* __restrict__ out, int n) {
    extern __shared__ float sm[];
    float* AS  = sm;                    // 64x132: AG -> staged D -> TH -> staged cf
    float* OUT = AS + NR * DSL;         // 64x128 (update, fp32)
    float* B2  = OUT + NR * 128;        // 64x132 (Th halves)
    float* muv = B2 + NR * DSL;
    float* rsv = muv + NR;

    int tid = threadIdx.x, lane = tid & 31, wid = tid >> 5;
    int g = lane >> 2, t = lane & 3;
    int rbase = (wid & 1) * 32;          // mw
    int wcol  = (wid >> 1) * 32;         // 4 col groups x 32
    int n0 = blockIdx.x * NR;

    // ---- load AG = agg/deg (tf32) ----
    for (int idx = tid; idx < NR * 32; idx += 256) {
        int r = idx >> 5, q = idx & 31;
        int nn = n0 + r; if (nn >= n) nn = n - 1;
        float4 a = ((const float4*)(g_agg + (size_t)nn * HDIM))[q];
        float inv = 1.0f / fmaxf(g_deg[nn], 1.0f);
        float* dst = AS + r * DSL + q * 4;
        dst[0] = rtf(a.x * inv); dst[1] = rtf(a.y * inv);
        dst[2] = rtf(a.z * inv); dst[3] = rtf(a.w * inv);
    }
    __syncthreads();

    float D4[2][4][4];
    // ---- GEMM: AG @ Wagg ----
    zeroD4(D4);
    wgemm2n<DSL, 128>(D4, AS, 16, g_WN + WAGG, wcol, rbase, g, t);
    __syncthreads();                 // AG reads done
    storeD4(D4, AS, rbase, wcol, g, t);
    __syncthreads();

    // ---- OUT = D + x + P[384:512] + bself + bagg (row-order) ----
    for (int r = wid; r < NR; r += 8) {
        int nn = n0 + r; int nc = (nn < n) ? nn : (n - 1);
        float4 d  = *(const float4*)(AS + r * DSL + lane * 4);
        float4 xv = __ldg((const float4*)(x + (size_t)nc * HDIM + lane * 4));
        float4 pv = __ldg((const float4*)(g_P + (size_t)nc * 512 + 384 + lane * 4));
        float4 b1 = __ldg((const float4*)(bself + lane * 4));
        float4 b2 = __ldg((const float4*)(bagg + lane * 4));
        *(float4*)(OUT + r * 128 + lane * 4) =
            make_float4(d.x + xv.x + pv.x + b1.x + b2.x,
                        d.y + xv.y + pv.y + b1.y + b2.y,
                        d.z + xv.z + pv.z + b1.z + b2.z,
                        d.w + xv.w + pv.w + b1.w + b2.w);
    }
    __syncthreads();

    // ---- LN2 stats (warp per row) ----
    for (int r = wid; r < NR; r += 8) {
        float4 v = *(const float4*)(OUT + r * 128 + lane * 4);
        float s = v.x + v.y + v.z + v.w;
#pragma unroll
        for (int o = 16; o; o >>= 1) s += __shfl_xor_sync(0xffffffffu, s, o);
        float m = s * (1.0f / 128.0f);
        float d0 = v.x - m, d1 = v.y - m, d2 = v.z - m, d3 = v.w - m;
        float q = d0 * d0 + d1 * d1 + d2 * d2 + d3 * d3;
#pragma unroll
        for (int o = 16; o; o >>= 1) q += __shfl_xor_sync(0xffffffffu, q, o);
        if (lane == 0) { muv[r] = m; rsv[r] = rsqrtf(q * (1.0f / 128.0f) + 1e-5f); }
    }
    __syncthreads();

    // ---- TH = rtf(LN2(OUT)) -> AS ----
    for (int idx = tid; idx < NR * 128; idx += 256) {
        int r = idx >> 7, c = idx & 127;
        AS[r * DSL + c] = rtf((OUT[r * 128 + c] - muv[r]) * rsv[r] * __ldg(ln2g + c) + __ldg(ln2b + c));
    }
    __syncthreads();

    // ---- FFN: cf = gelu(TH@Wf1 + bf1) @ Wf2 over two halves ----
    float cf[2][4][4];
    zeroD4(cf);
#pragma unroll 1
    for (int h = 0; h < 2; ++h) {
        float c2[2][4][4];
        zeroD4(c2);
        wgemm2n<DSL, 256>(c2, AS, 16, g_WN + WF1, h * 128 + wcol, rbase, g, t);
        __syncthreads();             // protect B2 (cf reads from prior half)
#pragma unroll
        for (int mt = 0; mt < 2; ++mt) {
            int r0 = rbase + mt * 16 + g, r1 = r0 + 8;
#pragma unroll
            for (int nt = 0; nt < 4; ++nt) {
                int c = wcol + nt * 8 + t * 2;
                float b0 = __ldg(bf1 + h * 128 + c), b1 = __ldg(bf1 + h * 128 + c + 1);
                *(float2*)(B2 + r0 * DSL + c) =
                    make_float2(rtf(gelu_f(c2[mt][nt][0] + b0)), rtf(gelu_f(c2[mt][nt][1] + b1)));
                *(float2*)(B2 + r1 * DSL + c) =
                    make_float2(rtf(gelu_f(c2[mt][nt][2] + b0)), rtf(gelu_f(c2[mt][nt][3] + b1)));
            }
        }
        __syncthreads();
        wgemm2n<DSL, 128>(cf, B2, 16, g_WN + WF2 + h * 8192, wcol, rbase, g, t);
    }
    storeD4(cf, AS, rbase, wcol, g, t);   // AS reads finished before last sync
    __syncthreads();

    // ---- final: out = cf + bf2 + OUT (row-order) ----
    for (int r = wid; r < NR; r += 8) {
        int nn = n0 + r;
        if (nn >= n) continue;
        float4 d = *(const float4*)(AS + r * DSL + lane * 4);
        float4 b = __ldg((const float4*)(bf2 + lane * 4));
        float4 o = *(const float4*)(OUT + r * 128 + lane * 4);
        *(float4*)(out + (size_t)nn * HDIM + lane * 4) =
            make_float4(d.x + b.x + o.x, d.y + b.y + o.y, d.z + b.z + o.z, d.w + b.w + o.w);
    }
}

// ---------------- launch ----------------
extern "C" void kernel_launch(void* const* d_in, const int* in_sizes, int n_in,
                              void* d_out, int out_size) {
    const float* x     = (const float*)d_in[0];
    const int*   esrc  = (const int*)d_in[1];
    const int*   edst  = (const int*)d_in[2];
    const float* eemb  = (const float*)d_in[3];
    const float* ln1g  = (const float*)d_in[4];
    const float* ln1b  = (const float*)d_in[5];
    const float* Wself = (const float*)d_in[6];
    const float* bself = (const float*)d_in[7];
    const float* Wm1   = (const float*)d_in[8];
    const float* bm1   = (const float*)d_in[9];
    const float* Wm2   = (const float*)d_in[10];
    const float* bm2   = (const float*)d_in[11];
    const float* Wg1   = (const float*)d_in[12];
    const float* bg1   = (const float*)d_in[13];
    const float* Wg2   = (const float*)d_in[14];
    const float* bg2   = (const float*)d_in[15];
    const float* Wagg  = (const float*)d_in[16];
    const float* bagg  = (const float*)d_in[17];
    const float* ln2g  = (const float*)d_in[18];
    const float* ln2b  = (const float*)d_in[19];
    const float* Wf1   = (const float*)d_in[20];
    const float* bf1   = (const float*)d_in[21];
    const float* Wf2   = (const float*)d_in[22];
    const float* bf2   = (const float*)d_in[23];

    int n = in_sizes[0] / HDIM;
    int E = in_sizes[1];
    float* out      = (float*)d_out;
    float* out_edge = out + (size_t)n * HDIM;

    const int PC_SMEM   = 128 * PLDA * 4;
    const int EDGE_SMEM = (128 * EA + 128 * DSL + 128) * 4 + 128 * 4 * 2;
    const int NODE_SMEM = (NR * DSL * 2 + NR * 128 + 2 * NR) * 4;
    cudaFuncSetAttribute(pcomp_kernel, cudaFuncAttributeMaxDynamicSharedMemorySize, PC_SMEM);
    cudaFuncSetAttribute(edge_kernel,  cudaFuncAttributeMaxDynamicSharedMemorySize, EDGE_SMEM);
    cudaFuncSetAttribute(node_kernel,  cudaFuncAttributeMaxDynamicSharedMemorySize, NODE_SMEM);

    prep_wt_kernel<<<(49152 + 255) / 256, 256>>>(Wg1, Wm1, Wm2, Wself);
    prep_wt2_kernel<<<(40960 + 255) / 256, 256>>>(Wagg, Wf1, Wf2);
    ln1_zero_kernel<<<(n + 7) / 8, 256>>>(x, ln1g, ln1b, n);
    dim3 pg((n + 127) / 128, 4);
    pcomp_kernel<<<pg, 256, PC_SMEM>>>(n);
    edge_kernel<<<(E + 127) / 128, 256, EDGE_SMEM>>>(
        esrc, edst, eemb, bg1, Wg2, bg2, bm1, bm2, out_edge, E);
    node_kernel<<<(n + NR - 1) / NR, 256, NODE_SMEM>>>(
        x, bself, bagg, ln2g, ln2b, bf1, bf2, out, n);
}

// round 12
// speedup vs baseline: 4.2311x; 1.0004x over previous
#include <cuda_runtime.h>
#include <math.h>
#include <stdint.h>

#define HDIM 128
#define MAXN 50000
#define MAXE 600064

// ---------------- device scratch ----------------
__device__ float g_h[(size_t)MAXN * HDIM];
__device__ float g_P[(size_t)MAXN * 512];
__device__ int g_cnt[MAXN];
__device__ int g_off[MAXN];
__device__ int g_cur[MAXN];
__device__ int g_eid[MAXE];
__device__ int g_blk[256];
// pair-interleaved tf32 weights: G[(ks*4+t)*NW + n] = (W[ks*8+t][n], W[ks*8+t+4][n])
__device__ uint2 g_WP[32768];   // pcomp: K=128, NW=512
__device__ uint2 g_WE[16384];   // gate-e(4096) | msg1-e(4096) | msg2(8192), NW=128
__device__ uint2 g_WN[40960];   // Wagg(8192) | Wf1(16384, NW=256) | Wf2(16384, K=256)
#define WAGG 0
#define WF1  8192
#define WF2  24576

// ---------------- helpers ----------------
__device__ __forceinline__ float gelu_f(float x) {
    return 0.5f * x * (1.0f + erff(x * 0.70710678118654752f));
}
__device__ __forceinline__ float rtf(float v) {
    uint32_t u; asm("cvt.rna.tf32.f32 %0, %1;" : "=r"(u) : "f"(v));
    return __uint_as_float(u);
}
__device__ __forceinline__ uint32_t rtfu(float v) {
    uint32_t u; asm("cvt.rna.tf32.f32 %0, %1;" : "=r"(u) : "f"(v));
    return u;
}
__device__ __forceinline__ void mma8(float* d, const uint32_t* a, const uint32_t* b) {
    asm volatile("mma.sync.aligned.m16n8k8.row.col.f32.tf32.tf32.f32 "
                 "{%0,%1,%2,%3}, {%4,%5,%6,%7}, {%8,%9}, {%0,%1,%2,%3};"
                 : "+f"(d[0]), "+f"(d[1]), "+f"(d[2]), "+f"(d[3])
                 : "r"(a[0]), "r"(a[1]), "r"(a[2]), "r"(a[3]), "r"(b[0]), "r"(b[1]));
}
__device__ __forceinline__ void zeroD(float D[2][8][4]) {
#pragma unroll
    for (int mt = 0; mt < 2; ++mt)
#pragma unroll
        for (int nt = 0; nt < 8; ++nt)
#pragma unroll
            for (int j = 0; j < 4; ++j) D[mt][nt][j] = 0.0f;
}
__device__ __forceinline__ void zeroD4(float D[2][4][4]) {
#pragma unroll
    for (int mt = 0; mt < 2; ++mt)
#pragma unroll
        for (int nt = 0; nt < 4; ++nt)
#pragma unroll
            for (int j = 0; j < 4; ++j) D[mt][nt][j] = 0.0f;
}

// Warp GEMM 32x64
template<int LDA, int NW>
__device__ __forceinline__ void wgemm2(float D[2][8][4], const float* As, int acol0, int ksteps,
                                       const uint2* W2, int wcol, int rbase, int g, int t) {
    const float* Ap = As + (rbase + g) * LDA + acol0 + t;
    const uint2* Wp = W2 + (size_t)t * NW + wcol + g;
#pragma unroll 4
    for (int ks = 0; ks < ksteps; ++ks) {
        uint32_t a[2][4];
        uint2 b[8];
        int ao = ks * 8;
#pragma unroll
        for (int mt = 0; mt < 2; ++mt) {
            const float* Am = Ap + mt * 16 * LDA;
            a[mt][0] = __float_as_uint(Am[ao]);
            a[mt][1] = __float_as_uint(Am[8 * LDA + ao]);
            a[mt][2] = __float_as_uint(Am[ao + 4]);
            a[mt][3] = __float_as_uint(Am[8 * LDA + ao + 4]);
        }
        const uint2* Wk = Wp + (size_t)ks * 4 * NW;
#pragma unroll
        for (int nt = 0; nt < 8; ++nt) b[nt] = __ldg(Wk + nt * 8);
#pragma unroll
        for (int mt = 0; mt < 2; ++mt)
#pragma unroll
            for (int nt = 0; nt < 8; ++nt)
                mma8(D[mt][nt], a[mt], (const uint32_t*)&b[nt]);
    }
}

// Warp GEMM 32x32
template<int LDA, int NW>
__device__ __forceinline__ void wgemm2n(float D[2][4][4], const float* As, int ksteps,
                                        const uint2* W2, int wcol, int rbase, int g, int t) {
    const float* Ap = As + (rbase + g) * LDA + t;
    const uint2* Wp = W2 + (size_t)t * NW + wcol + g;
#pragma unroll 4
    for (int ks = 0; ks < ksteps; ++ks) {
        uint32_t a[2][4];
        uint2 b[4];
        int ao = ks * 8;
#pragma unroll
        for (int mt = 0; mt < 2; ++mt) {
            const float* Am = Ap + mt * 16 * LDA;
            a[mt][0] = __float_as_uint(Am[ao]);
            a[mt][1] = __float_as_uint(Am[8 * LDA + ao]);
            a[mt][2] = __float_as_uint(Am[ao + 4]);
            a[mt][3] = __float_as_uint(Am[8 * LDA + ao + 4]);
        }
        const uint2* Wk = Wp + (size_t)ks * 4 * NW;
#pragma unroll
        for (int nt = 0; nt < 4; ++nt) b[nt] = __ldg(Wk + nt * 8);
#pragma unroll
        for (int mt = 0; mt < 2; ++mt)
#pragma unroll
            for (int nt = 0; nt < 4; ++nt)
                mma8(D[mt][nt], a[mt], (const uint32_t*)&b[nt]);
    }
}

#define DSL 132
__device__ __forceinline__ void storeD(float D[2][8][4], float* DS,
                                       int rbase, int cbase, int g, int t) {
#pragma unroll
    for (int mt = 0; mt < 2; ++mt) {
        int r0 = rbase + mt * 16 + g, r1 = r0 + 8;
#pragma unroll
        for (int nt = 0; nt < 8; ++nt) {
            int c = cbase + nt * 8 + t * 2;
            *(float2*)(DS + r0 * DSL + c) = make_float2(D[mt][nt][0], D[mt][nt][1]);
            *(float2*)(DS + r1 * DSL + c) = make_float2(D[mt][nt][2], D[mt][nt][3]);
        }
    }
}
__device__ __forceinline__ void storeD4(float D[2][4][4], float* DS,
                                        int rbase, int cbase, int g, int t) {
#pragma unroll
    for (int mt = 0; mt < 2; ++mt) {
        int r0 = rbase + mt * 16 + g, r1 = r0 + 8;
#pragma unroll
        for (int nt = 0; nt < 4; ++nt) {
            int c = cbase + nt * 8 + t * 2;
            *(float2*)(DS + r0 * DSL + c) = make_float2(D[mt][nt][0], D[mt][nt][1]);
            *(float2*)(DS + r1 * DSL + c) = make_float2(D[mt][nt][2], D[mt][nt][3]);
        }
    }
}

// ---------------- Kernel 0a: pcomp/edge weights ----------------
__global__ void prep_wt_kernel(const float* __restrict__ Wg1, const float* __restrict__ Wm1,
                               const float* __restrict__ Wm2, const float* __restrict__ Wself) {
    int idx = blockIdx.x * 256 + threadIdx.x;
    if (idx >= 49152) return;
    if (idx < 32768) {
        int ks = idx >> 11, t = (idx >> 9) & 3, n = idx & 511;
        int k = ks * 8 + t;
        float v0, v1;
        if (n < 128)      { v0 = Wg1[k * 128 + n];           v1 = Wg1[(k + 4) * 128 + n]; }
        else if (n < 256) { v0 = Wg1[(128 + k) * 128 + n - 128]; v1 = Wg1[(132 + k) * 128 + n - 128]; }
        else if (n < 384) { v0 = Wm1[k * 128 + n - 256];     v1 = Wm1[(k + 4) * 128 + n - 256]; }
        else              { v0 = Wself[k * 128 + n - 384];   v1 = Wself[(k + 4) * 128 + n - 384]; }
        g_WP[idx] = make_uint2(rtfu(v0), rtfu(v1));
    } else {
        int j = idx - 32768;
        int seg = (j < 4096) ? 0 : (j < 8192 ? 1 : 2);
        int j2 = j - (seg == 0 ? 0 : (seg == 1 ? 4096 : 8192));
        int ks = j2 >> 9, t = (j2 >> 7) & 3, n = j2 & 127;
        int k = ks * 8 + t;
        float v0, v1;
        if (seg == 0)      { v0 = Wg1[(256 + k) * 128 + n]; v1 = Wg1[(260 + k) * 128 + n]; }
        else if (seg == 1) { v0 = Wm1[(128 + k) * 128 + n]; v1 = Wm1[(132 + k) * 128 + n]; }
        else               { v0 = Wm2[k * 128 + n];         v1 = Wm2[(k + 4) * 128 + n]; }
        g_WE[j] = make_uint2(rtfu(v0), rtfu(v1));
    }
}

// ---------------- Kernel 0b: node weights ----------------
__global__ void prep_wt2_kernel(const float* __restrict__ Wagg,
                                const float* __restrict__ Wf1,
                                const float* __restrict__ Wf2) {
    int idx = blockIdx.x * 256 + threadIdx.x;
    if (idx >= 40960) return;
    float v0, v1;
    if (idx < 8192) {
        int ks = idx >> 9, t = (idx >> 7) & 3, n = idx & 127;
        int k = ks * 8 + t;
        v0 = Wagg[k * 128 + n]; v1 = Wagg[(k + 4) * 128 + n];
        g_WN[idx] = make_uint2(rtfu(v0), rtfu(v1));
    } else if (idx < 24576) {
        int j = idx - 8192;
        int ks = j >> 10, t = (j >> 8) & 3, n = j & 255;
        int k = ks * 8 + t;
        v0 = Wf1[k * 256 + n]; v1 = Wf1[(k + 4) * 256 + n];
        g_WN[idx] = make_uint2(rtfu(v0), rtfu(v1));
    } else {
        int j = idx - 24576;
        int ks = j >> 9, t = (j >> 7) & 3, n = j & 127;
        int k = ks * 8 + t;
        v0 = Wf2[k * 128 + n]; v1 = Wf2[(k + 4) * 128 + n];
        g_WN[idx] = make_uint2(rtfu(v0), rtfu(v1));
    }
}

// ---------------- Kernel 1: LN(x) -> g_h; zero cnt ----------------
__global__ void ln1_zero_kernel(const float* __restrict__ x,
                                const float* __restrict__ g, const float* __restrict__ b, int n) {
    int row = blockIdx.x * 8 + (threadIdx.x >> 5);
    int lane = threadIdx.x & 31;
    if (row >= n) return;
    float4 v = ((const float4*)(x + (size_t)row * HDIM))[lane];
    float s = v.x + v.y + v.z + v.w;
#pragma unroll
    for (int o = 16; o; o >>= 1) s += __shfl_xor_sync(0xffffffffu, s, o);
    float m = s * (1.0f / 128.0f);
    float dx = v.x - m, dy = v.y - m, dz = v.z - m, dw = v.w - m;
    float q = dx * dx + dy * dy + dz * dz + dw * dw;
#pragma unroll
    for (int o = 16; o; o >>= 1) q += __shfl_xor_sync(0xffffffffu, q, o);
    float rstd = rsqrtf(q * (1.0f / 128.0f) + 1e-5f);
    float4 gv = ((const float4*)g)[lane];
    float4 bv = ((const float4*)b)[lane];
    float4 h;
    h.x = dx * rstd * gv.x + bv.x;
    h.y = dy * rstd * gv.y + bv.y;
    h.z = dz * rstd * gv.z + bv.z;
    h.w = dw * rstd * gv.w + bv.w;
    ((float4*)(g_h + (size_t)row * HDIM))[lane] = h;
    if (lane == 0) g_cnt[row] = 0;
}

// ---------------- CSR build: hist / scan / fill ----------------
__global__ void hist_kernel(const int* __restrict__ edst, int E_) {
    int i = blockIdx.x * 256 + threadIdx.x;
    if (i < E_) atomicAdd(&g_cnt[edst[i]], 1);
}

__global__ void scan1_kernel(int n) {
    __shared__ int wsum[8];
    int i = blockIdx.x * 256 + threadIdx.x;
    int lane = threadIdx.x & 31, w = threadIdx.x >> 5;
    int v = (i < n) ? g_cnt[i] : 0;
    int s = v;
#pragma unroll
    for (int o = 1; o < 32; o <<= 1) {
        int t = __shfl_up_sync(0xffffffffu, s, o);
        if (lane >= o) s += t;
    }
    if (lane == 31) wsum[w] = s;
    __syncthreads();
    if (w == 0) {
        int t = (lane < 8) ? wsum[lane] : 0;
#pragma unroll
        for (int o = 1; o < 8; o <<= 1) {
            int u = __shfl_up_sync(0xffffffffu, t, o);
            if (lane >= o) t += u;
        }
        if (lane < 8) wsum[lane] = t;
    }
    __syncthreads();
    int excl = s - v + (w > 0 ? wsum[w - 1] : 0);
    if (i < n) g_off[i] = excl;
    if (threadIdx.x == 0) g_blk[blockIdx.x] = wsum[7];
}

__global__ void scan2_kernel(int B) {
    __shared__ int wsum[8];
    int tid = threadIdx.x;
    int lane = tid & 31, w = tid >> 5;
    int v = (tid < B) ? g_blk[tid] : 0;
    int s = v;
#pragma unroll
    for (int o = 1; o < 32; o <<= 1) {
        int t = __shfl_up_sync(0xffffffffu, s, o);
        if (lane >= o) s += t;
    }
    if (lane == 31) wsum[w] = s;
    __syncthreads();
    if (w == 0) {
        int t = (lane < 8) ? wsum[lane] : 0;
#pragma unroll
        for (int o = 1; o < 8; o <<= 1) {
            int u = __shfl_up_sync(0xffffffffu, t, o);
            if (lane >= o) t += u;
        }
        if (lane < 8) wsum[lane] = t;
    }
    __syncthreads();
    int excl = s - v + (w > 0 ? wsum[w - 1] : 0);
    if (tid < B) g_blk[tid] = excl;
}

__global__ void scan3_kernel(int n) {
    int i = blockIdx.x * 256 + threadIdx.x;
    if (i < n) {
        int o = g_off[i] + g_blk[blockIdx.x];
        g_off[i] = o;
        g_cur[i] = o;
    }
}

__global__ void fill_kernel(const int* __restrict__ edst, int E_) {
    int i = blockIdx.x * 256 + threadIdx.x;
    if (i < E_) {
        int pos = atomicAdd(&g_cur[edst[i]], 1);
        g_eid[pos] = i;
    }
}

// ---------------- Kernel 2: P = h @ [Wg1a|Wg1b|Wm1a|Wself] ----------------
#define PLDA 132
__global__ __launch_bounds__(256, 2) void pcomp_kernel(int n) {
    extern __shared__ float As[];
    int tid = threadIdx.x, lane = tid & 31, wid = tid >> 5;
    int g = lane >> 2, t = lane & 3;
    int rbase = (wid >> 1) * 32, cbase = (wid & 1) * 64;
    int n0 = blockIdx.x * 128;
    int wcol = blockIdx.y * 128 + cbase;

    for (int idx = tid; idx < 128 * 32; idx += 256) {
        int r = idx >> 5, q = idx & 31;
        int nn = n0 + r; if (nn >= n) nn = n - 1;
        float4 v = ((const float4*)(g_h + (size_t)nn * HDIM))[q];
        float* dst = As + r * PLDA + q * 4;
        dst[0] = rtf(v.x); dst[1] = rtf(v.y); dst[2] = rtf(v.z); dst[3] = rtf(v.w);
    }
    __syncthreads();

    float D[2][8][4];
    zeroD(D);
    wgemm2<PLDA, 512>(D, As, 0, 16, g_WP, wcol, rbase, g, t);

#pragma unroll
    for (int mt = 0; mt < 2; ++mt) {
        int r0 = rbase + mt * 16 + g;
        int rr0 = n0 + r0, rr1 = rr0 + 8;
#pragma unroll
        for (int nt = 0; nt < 8; ++nt) {
            int c = wcol + nt * 8 + t * 2;
            if (rr0 < n) *(float2*)(g_P + (size_t)rr0 * 512 + c) = make_float2(D[mt][nt][0], D[mt][nt][1]);
            if (rr1 < n) *(float2*)(g_P + (size_t)rr1 * 512 + c) = make_float2(D[mt][nt][2], D[mt][nt][3]);
        }
    }
}

// ---------------- Kernel 3: edge MLPs (no scatter) ----------------
#define EA 68
__global__ __launch_bounds__(256, 2) void edge_kernel(
    const int* __restrict__ esrc, const int* __restrict__ edst,
    const float* __restrict__ eemb,
    const float* __restrict__ bg1, const float* __restrict__ Wg2, const float* __restrict__ bg2,
    const float* __restrict__ bm1, const float* __restrict__ bm2,
    float* __restrict__ out_edge, int E_) {
    extern __shared__ float sm[];
    float* Ae = sm;                   // 128 x 68 (e, tf32)
    float* DS = sm + 128 * EA;        // 128 x 132 (staged D / Z)
    float* gs = DS + 128 * DSL;       // 128
    int* esm = (int*)(gs + 128);
    int* edm = esm + 128;

    int tid = threadIdx.x, lane = tid & 31, wid = tid >> 5;
    int g = lane >> 2, t = lane & 3;
    int rbase = (wid >> 1) * 32, cbase = (wid & 1) * 64;
    long long e0 = (long long)blockIdx.x * 128;

    if (tid < 128) {
        long long eg = e0 + tid;
        int cl = (eg < E_) ? (int)eg : (E_ - 1);
        esm[tid] = esrc[cl]; edm[tid] = edst[cl];
    }
    __syncthreads();

    for (int idx = tid; idx < 128 * 16; idx += 256) {
        int r = idx >> 4, q = idx & 15;
        long long eg = e0 + r; if (eg >= E_) eg = E_ - 1;
        float4 v = ((const float4*)(eemb + eg * 64))[q];
        float* dst = Ae + r * EA + q * 4;
        dst[0] = rtf(v.x); dst[1] = rtf(v.y); dst[2] = rtf(v.z); dst[3] = rtf(v.w);
    }
    __syncthreads();

    float D[2][8][4];

    // ---- GEMM1: gate e-part -> DS ----
    zeroD(D);
    wgemm2<EA, 128>(D, Ae, 0, 8, g_WE, cbase, rbase, g, t);
    storeD(D, DS, rbase, cbase, g, t);
    __syncthreads();

    // ---- gate pass ----
    for (int r = wid; r < 128; r += 8) {
        const float* Pd = g_P + (size_t)edm[r] * 512;
        const float* Ps = g_P + (size_t)esm[r] * 512 + 128;
        float4 de = *(const float4*)(DS + r * DSL + lane * 4);
        float4 pd = __ldg((const float4*)(Pd + lane * 4));
        float4 ps = __ldg((const float4*)(Ps + lane * 4));
        float4 bb = __ldg((const float4*)(bg1 + lane * 4));
        float4 ww = __ldg((const float4*)(Wg2 + lane * 4));
        float s = gelu_f(de.x + pd.x + ps.x + bb.x) * ww.x
                + gelu_f(de.y + pd.y + ps.y + bb.y) * ww.y
                + gelu_f(de.z + pd.z + ps.z + bb.z) * ww.z
                + gelu_f(de.w + pd.w + ps.w + bb.w) * ww.w;
#pragma unroll
        for (int o = 16; o; o >>= 1) s += __shfl_xor_sync(0xffffffffu, s, o);
        if (lane == 0) gs[r] = s;
    }
    __syncthreads();

    // ---- GEMM2: msg1 e-part -> DS ----
    zeroD(D);
    wgemm2<EA, 128>(D, Ae, 0, 8, g_WE + 4096, cbase, rbase, g, t);
    storeD(D, DS, rbase, cbase, g, t);
    __syncthreads();

    // ---- msg1 pass: Z in-place ----
    for (int r = wid; r < 128; r += 8) {
        const float* Pm = g_P + (size_t)esm[r] * 512 + 256;
        float* row = DS + r * DSL + lane * 4;
        float4 d = *(const float4*)row;
        float4 pm = __ldg((const float4*)(Pm + lane * 4));
        float4 bb = __ldg((const float4*)(bm1 + lane * 4));
        *(float4*)row = make_float4(rtf(gelu_f(d.x + pm.x + bb.x)),
                                    rtf(gelu_f(d.y + pm.y + bb.y)),
                                    rtf(gelu_f(d.z + pm.z + bb.z)),
                                    rtf(gelu_f(d.w + pm.w + bb.w)));
    }
    __syncthreads();

    // ---- GEMM3: msg2 = Z @ Wm2 ----
    zeroD(D);
    wgemm2<DSL, 128>(D, DS, 0, 16, g_WE + 8192, cbase, rbase, g, t);
    __syncthreads();
    storeD(D, DS, rbase, cbase, g, t);
    __syncthreads();

    // ---- final: edge_repr only (no atomics) ----
    float bg2v = __ldg(bg2);
    for (int r = wid; r < 128; r += 8) {
        long long eg = e0 + r;
        if (eg >= E_) continue;
        float gt = 1.0f / (1.0f + expf(-(gs[r] + bg2v)));
        float4 d = *(const float4*)(DS + r * DSL + lane * 4);
        float4 bb = __ldg((const float4*)(bm2 + lane * 4));
        *(float4*)(out_edge + eg * 128 + lane * 4) =
            make_float4((d.x + bb.x) * gt, (d.y + bb.y) * gt,
                        (d.z + bb.z) * gt, (d.w + bb.w) * gt);
    }
}

// ---------------- Kernel 4: node update + FFN (mma) with CSR gather ----------------
#define NR 64
__global__ __launch_bounds__(256, 2) void node_kernel(
    const float* __restrict__ x, const float* __restrict__ out_edge,
    const float* __restrict__ bself, const float* __restrict__ bagg,
    const float* __restrict__ ln2g,  const float* __restrict__ ln2b,
    const float* __restrict__ bf1,   const float* __restrict__ bf2,
    float* __restrict__ out, int n) {
    extern __shared__ float sm[];
    float* AS  = sm;                    // 64x132
    float* OUT = AS + NR * DSL;         // 64x128
    float* B2  = OUT + NR * 128;        // 64x132
    float* muv = B2 + NR * DSL;
    float* rsv = muv + NR;

    int tid = threadIdx.x, lane = tid & 31, wid = tid >> 5;
    int g = lane >> 2, t = lane & 3;
    int rbase = (wid & 1) * 32;
    int wcol  = (wid >> 1) * 32;
    int n0 = blockIdx.x * NR;

    // ---- CSR aggregation: AG = mean of incoming edge_repr rows (tf32) ----
    for (int r = wid; r < NR; r += 8) {
        int nn = n0 + r; if (nn >= n) nn = n - 1;
        int off = __ldg(&g_off[nn]);
        int c   = __ldg(&g_cnt[nn]);
        float4 a0 = make_float4(0.f, 0.f, 0.f, 0.f);
        float4 a1 = make_float4(0.f, 0.f, 0.f, 0.f);
        int j = 0;
        for (; j + 1 < c; j += 2) {
            int e0 = __ldg(&g_eid[off + j]), e1 = __ldg(&g_eid[off + j + 1]);
            float4 v0 = __ldg((const float4*)(out_edge + (size_t)e0 * 128 + lane * 4));
            float4 v1 = __ldg((const float4*)(out_edge + (size_t)e1 * 128 + lane * 4));
            a0.x += v0.x; a0.y += v0.y; a0.z += v0.z; a0.w += v0.w;
            a1.x += v1.x; a1.y += v1.y; a1.z += v1.z; a1.w += v1.w;
        }
        if (j < c) {
            int e0 = __ldg(&g_eid[off + j]);
            float4 v0 = __ldg((const float4*)(out_edge + (size_t)e0 * 128 + lane * 4));
            a0.x += v0.x; a0.y += v0.y; a0.z += v0.z; a0.w += v0.w;
        }
        float inv = 1.0f / fmaxf((float)c, 1.0f);
        float* dst = AS + r * DSL + lane * 4;
        dst[0] = rtf((a0.x + a1.x) * inv); dst[1] = rtf((a0.y + a1.y) * inv);
        dst[2] = rtf((a0.z + a1.z) * inv); dst[3] = rtf((a0.w + a1.w) * inv);
    }
    __syncthreads();

    float D4[2][4][4];
    zeroD4(D4);
    wgemm2n<DSL, 128>(D4, AS, 16, g_WN + WAGG, wcol, rbase, g, t);
    __syncthreads();
    storeD4(D4, AS, rbase, wcol, g, t);
    __syncthreads();

    // ---- OUT = D + x + P[384:512] + bself + bagg ----
    for (int r = wid; r < NR; r += 8) {
        int nn = n0 + r; int nc = (nn < n) ? nn : (n - 1);
        float4 d  = *(const float4*)(AS + r * DSL + lane * 4);
        float4 xv = __ldg((const float4*)(x + (size_t)nc * HDIM + lane * 4));
        float4 pv = __ldg((const float4*)(g_P + (size_t)nc * 512 + 384 + lane * 4));
        float4 b1 = __ldg((const float4*)(bself + lane * 4));
        float4 b2 = __ldg((const float4*)(bagg + lane * 4));
        *(float4*)(OUT + r * 128 + lane * 4) =
            make_float4(d.x + xv.x + pv.x + b1.x + b2.x,
                        d.y + xv.y + pv.y + b1.y + b2.y,
                        d.z + xv.z + pv.z + b1.z + b2.z,
                        d.w + xv.w + pv.w + b1.w + b2.w);
    }
    __syncthreads();

    // ---- LN2 stats ----
    for (int r = wid; r < NR; r += 8) {
        float4 v = *(const float4*)(OUT + r * 128 + lane * 4);
        float s = v.x + v.y + v.z + v.w;
#pragma unroll
        for (int o = 16; o; o >>= 1) s += __shfl_xor_sync(0xffffffffu, s, o);
        float m = s * (1.0f / 128.0f);
        float d0 = v.x - m, d1 = v.y - m, d2 = v.z - m, d3 = v.w - m;
        float q = d0 * d0 + d1 * d1 + d2 * d2 + d3 * d3;
#pragma unroll
        for (int o = 16; o; o >>= 1) q += __shfl_xor_sync(0xffffffffu, q, o);
        if (lane == 0) { muv[r] = m; rsv[r] = rsqrtf(q * (1.0f / 128.0f) + 1e-5f); }
    }
    __syncthreads();

    // ---- TH = rtf(LN2(OUT)) -> AS ----
    for (int idx = tid; idx < NR * 128; idx += 256) {
        int r = idx >> 7, c = idx & 127;
        AS[r * DSL + c] = rtf((OUT[r * 128 + c] - muv[r]) * rsv[r] * __ldg(ln2g + c) + __ldg(ln2b + c));
    }
    __syncthreads();

    // ---- FFN ----
    float cf[2][4][4];
    zeroD4(cf);
#pragma unroll 1
    for (int h = 0; h < 2; ++h) {
        float c2[2][4][4];
        zeroD4(c2);
        wgemm2n<DSL, 256>(c2, AS, 16, g_WN + WF1, h * 128 + wcol, rbase, g, t);
        __syncthreads();
#pragma unroll
        for (int mt = 0; mt < 2; ++mt) {
            int r0 = rbase + mt * 16 + g, r1 = r0 + 8;
#pragma unroll
            for (int nt = 0; nt < 4; ++nt) {
                int c = wcol + nt * 8 + t * 2;
                float b0 = __ldg(bf1 + h * 128 + c), b1 = __ldg(bf1 + h * 128 + c + 1);
                *(float2*)(B2 + r0 * DSL + c) =
                    make_float2(rtf(gelu_f(c2[mt][nt][0] + b0)), rtf(gelu_f(c2[mt][nt][1] + b1)));
                *(float2*)(B2 + r1 * DSL + c) =
                    make_float2(rtf(gelu_f(c2[mt][nt][2] + b0)), rtf(gelu_f(c2[mt][nt][3] + b1)));
            }
        }
        __syncthreads();
        wgemm2n<DSL, 128>(cf, B2, 16, g_WN + WF2 + h * 8192, wcol, rbase, g, t);
    }
    storeD4(cf, AS, rbase, wcol, g, t);
    __syncthreads();

    // ---- final ----
    for (int r = wid; r < NR; r += 8) {
        int nn = n0 + r;
        if (nn >= n) continue;
        float4 d = *(const float4*)(AS + r * DSL + lane * 4);
        float4 b = __ldg((const float4*)(bf2 + lane * 4));
        float4 o = *(const float4*)(OUT + r * 128 + lane * 4);
        *(float4*)(out + (size_t)nn * HDIM + lane * 4) =
            make_float4(d.x + b.x + o.x, d.y + b.y + o.y, d.z + b.z + o.z, d.w + b.w + o.w);
    }
}

// ---------------- launch ----------------
extern "C" void kernel_launch(void* const* d_in, const int* in_sizes, int n_in,
                              void* d_out, int out_size) {
    const float* x     = (const float*)d_in[0];
    const int*   esrc  = (const int*)d_in[1];
    const int*   edst  = (const int*)d_in[2];
    const float* eemb  = (const float*)d_in[3];
    const float* ln1g  = (const float*)d_in[4];
    const float* ln1b  = (const float*)d_in[5];
    const float* Wself = (const float*)d_in[6];
    const float* bself = (const float*)d_in[7];
    const float* Wm1   = (const float*)d_in[8];
    const float* bm1   = (const float*)d_in[9];
    const float* Wm2   = (const float*)d_in[10];
    const float* bm2   = (const float*)d_in[11];
    const float* Wg1   = (const float*)d_in[12];
    const float* bg1   = (const float*)d_in[13];
    const float* Wg2   = (const float*)d_in[14];
    const float* bg2   = (const float*)d_in[15];
    const float* Wagg  = (const float*)d_in[16];
    const float* bagg  = (const float*)d_in[17];
    const float* ln2g  = (const float*)d_in[18];
    const float* ln2b  = (const float*)d_in[19];
    const float* Wf1   = (const float*)d_in[20];
    const float* bf1   = (const float*)d_in[21];
    const float* Wf2   = (const float*)d_in[22];
    const float* bf2   = (const float*)d_in[23];

    int n = in_sizes[0] / HDIM;
    int E = in_sizes[1];
    float* out      = (float*)d_out;
    float* out_edge = out + (size_t)n * HDIM;
    int B = (n + 255) / 256;

    const int PC_SMEM   = 128 * PLDA * 4;
    const int EDGE_SMEM = (128 * EA + 128 * DSL + 128) * 4 + 128 * 4 * 2;
    const int NODE_SMEM = (NR * DSL * 2 + NR * 128 + 2 * NR) * 4;
    cudaFuncSetAttribute(pcomp_kernel, cudaFuncAttributeMaxDynamicSharedMemorySize, PC_SMEM);
    cudaFuncSetAttribute(edge_kernel,  cudaFuncAttributeMaxDynamicSharedMemorySize, EDGE_SMEM);
    cudaFuncSetAttribute(node_kernel,  cudaFuncAttributeMaxDynamicSharedMemorySize, NODE_SMEM);

    prep_wt_kernel<<<(49152 + 255) / 256, 256>>>(Wg1, Wm1, Wm2, Wself);
    prep_wt2_kernel<<<(40960 + 255) / 256, 256>>>(Wagg, Wf1, Wf2);
    ln1_zero_kernel<<<(n + 7) / 8, 256>>>(x, ln1g, ln1b, n);
    hist_kernel<<<(E + 255) / 256, 256>>>(edst, E);
    scan1_kernel<<<B, 256>>>(n);
    scan2_kernel<<<1, 256>>>(B);
    scan3_kernel<<<B, 256>>>(n);
    fill_kernel<<<(E + 255) / 256, 256>>>(edst, E);
    dim3 pg((n + 127) / 128, 4);
    pcomp_kernel<<<pg, 256, PC_SMEM>>>(n);
    edge_kernel<<<(E + 127) / 128, 256, EDGE_SMEM>>>(
        esrc, edst, eemb, bg1, Wg2, bg2, bm1, bm2, out_edge, E);
    node_kernel<<<(n + NR - 1) / NR, 256, NODE_SMEM>>>(
        x, out_edge, bself, bagg, ln2g, ln2b, bf1, bf2, out, n);
}

// round 15
// speedup vs baseline: 4.3983x; 1.0395x over previous
#include <cuda_runtime.h>
#include <math.h>
#include <stdint.h>

#define HDIM 128
#define MAXN 50000
#define MAXE 600064

// ---------------- device scratch ----------------
__device__ float g_h[(size_t)MAXN * HDIM];
__device__ float g_P[(size_t)MAXN * 512];
__device__ int g_cnt[MAXN];
__device__ int g_off[MAXN];
__device__ int g_cur[MAXN];
__device__ int g_eid[MAXE];
__device__ int g_blk[256];
__device__ uint2 g_WP[32768];   // pcomp: K=128, NW=512
__device__ uint2 g_WE[16384];   // gate-e(4096) | msg1-e(4096) | msg2(8192), NW=128
__device__ uint2 g_WN[40960];   // Wagg(8192) | Wf1(16384, NW=256) | Wf2(16384, K=256)
#define WAGG 0
#define WF1  8192
#define WF2  24576

// ---------------- helpers ----------------
__device__ __forceinline__ float gelu_f(float x) {
    return 0.5f * x * (1.0f + erff(x * 0.70710678118654752f));
}
__device__ __forceinline__ float rtf(float v) {
    uint32_t u; asm("cvt.rna.tf32.f32 %0, %1;" : "=r"(u) : "f"(v));
    return __uint_as_float(u);
}
__device__ __forceinline__ uint32_t rtfu(float v) {
    uint32_t u; asm("cvt.rna.tf32.f32 %0, %1;" : "=r"(u) : "f"(v));
    return u;
}
__device__ __forceinline__ void mma8(float* d, const uint32_t* a, const uint32_t* b) {
    asm volatile("mma.sync.aligned.m16n8k8.row.col.f32.tf32.tf32.f32 "
                 "{%0,%1,%2,%3}, {%4,%5,%6,%7}, {%8,%9}, {%0,%1,%2,%3};"
                 : "+f"(d[0]), "+f"(d[1]), "+f"(d[2]), "+f"(d[3])
                 : "r"(a[0]), "r"(a[1]), "r"(a[2]), "r"(a[3]), "r"(b[0]), "r"(b[1]));
}
__device__ __forceinline__ void zeroD(float D[2][8][4]) {
#pragma unroll
    for (int mt = 0; mt < 2; ++mt)
#pragma unroll
        for (int nt = 0; nt < 8; ++nt)
#pragma unroll
            for (int j = 0; j < 4; ++j) D[mt][nt][j] = 0.0f;
}
__device__ __forceinline__ void zeroD4(float D[2][4][4]) {
#pragma unroll
    for (int mt = 0; mt < 2; ++mt)
#pragma unroll
        for (int nt = 0; nt < 4; ++nt)
#pragma unroll
            for (int j = 0; j < 4; ++j) D[mt][nt][j] = 0.0f;
}

// Warp GEMM 32x64
template<int LDA, int NW>
__device__ __forceinline__ void wgemm2(float D[2][8][4], const float* As, int acol0, int ksteps,
                                       const uint2* W2, int wcol, int rbase, int g, int t) {
    const float* Ap = As + (rbase + g) * LDA + acol0 + t;
    const uint2* Wp = W2 + (size_t)t * NW + wcol + g;
#pragma unroll 4
    for (int ks = 0; ks < ksteps; ++ks) {
        uint32_t a[2][4];
        uint2 b[8];
        int ao = ks * 8;
#pragma unroll
        for (int mt = 0; mt < 2; ++mt) {
            const float* Am = Ap + mt * 16 * LDA;
            a[mt][0] = __float_as_uint(Am[ao]);
            a[mt][1] = __float_as_uint(Am[8 * LDA + ao]);
            a[mt][2] = __float_as_uint(Am[ao + 4]);
            a[mt][3] = __float_as_uint(Am[8 * LDA + ao + 4]);
        }
        const uint2* Wk = Wp + (size_t)ks * 4 * NW;
#pragma unroll
        for (int nt = 0; nt < 8; ++nt) b[nt] = __ldg(Wk + nt * 8);
#pragma unroll
        for (int mt = 0; mt < 2; ++mt)
#pragma unroll
            for (int nt = 0; nt < 8; ++nt)
                mma8(D[mt][nt], a[mt], (const uint32_t*)&b[nt]);
    }
}

// Warp GEMM 32x32
template<int LDA, int NW>
__device__ __forceinline__ void wgemm2n(float D[2][4][4], const float* As, int ksteps,
                                        const uint2* W2, int wcol, int rbase, int g, int t) {
    const float* Ap = As + (rbase + g) * LDA + t;
    const uint2* Wp = W2 + (size_t)t * NW + wcol + g;
#pragma unroll 4
    for (int ks = 0; ks < ksteps; ++ks) {
        uint32_t a[2][4];
        uint2 b[4];
        int ao = ks * 8;
#pragma unroll
        for (int mt = 0; mt < 2; ++mt) {
            const float* Am = Ap + mt * 16 * LDA;
            a[mt][0] = __float_as_uint(Am[ao]);
            a[mt][1] = __float_as_uint(Am[8 * LDA + ao]);
            a[mt][2] = __float_as_uint(Am[ao + 4]);
            a[mt][3] = __float_as_uint(Am[8 * LDA + ao + 4]);
        }
        const uint2* Wk = Wp + (size_t)ks * 4 * NW;
#pragma unroll
        for (int nt = 0; nt < 4; ++nt) b[nt] = __ldg(Wk + nt * 8);
#pragma unroll
        for (int mt = 0; mt < 2; ++mt)
#pragma unroll
            for (int nt = 0; nt < 4; ++nt)
                mma8(D[mt][nt], a[mt], (const uint32_t*)&b[nt]);
    }
}

#define DSL 132
__device__ __forceinline__ void storeD(float D[2][8][4], float* DS,
                                       int rbase, int cbase, int g, int t) {
#pragma unroll
    for (int mt = 0; mt < 2; ++mt) {
        int r0 = rbase + mt * 16 + g, r1 = r0 + 8;
#pragma unroll
        for (int nt = 0; nt < 8; ++nt) {
            int c = cbase + nt * 8 + t * 2;
            *(float2*)(DS + r0 * DSL + c) = make_float2(D[mt][nt][0], D[mt][nt][1]);
            *(float2*)(DS + r1 * DSL + c) = make_float2(D[mt][nt][2], D[mt][nt][3]);
        }
    }
}
__device__ __forceinline__ void storeD4(float D[2][4][4], float* DS,
                                        int rbase, int cbase, int g, int t) {
#pragma unroll
    for (int mt = 0; mt < 2; ++mt) {
        int r0 = rbase + mt * 16 + g, r1 = r0 + 8;
#pragma unroll
        for (int nt = 0; nt < 4; ++nt) {
            int c = cbase + nt * 8 + t * 2;
            *(float2*)(DS + r0 * DSL + c) = make_float2(D[mt][nt][0], D[mt][nt][1]);
            *(float2*)(DS + r1 * DSL + c) = make_float2(D[mt][nt][2], D[mt][nt][3]);
        }
    }
}

// ---------------- Kernel 0a: pcomp/edge weights ----------------
__global__ void prep_wt_kernel(const float* __restrict__ Wg1, const float* __restrict__ Wm1,
                               const float* __restrict__ Wm2, const float* __restrict__ Wself) {
    int idx = blockIdx.x * 256 + threadIdx.x;
    if (idx >= 49152) return;
    if (idx < 32768) {
        int ks = idx >> 11, t = (idx >> 9) & 3, n = idx & 511;
        int k = ks * 8 + t;
        float v0, v1;
        if (n < 128)      { v0 = Wg1[k * 128 + n];           v1 = Wg1[(k + 4) * 128 + n]; }
        else if (n < 256) { v0 = Wg1[(128 + k) * 128 + n - 128]; v1 = Wg1[(132 + k) * 128 + n - 128]; }
        else if (n < 384) { v0 = Wm1[k * 128 + n - 256];     v1 = Wm1[(k + 4) * 128 + n - 256]; }
        else              { v0 = Wself[k * 128 + n - 384];   v1 = Wself[(k + 4) * 128 + n - 384]; }
        g_WP[idx] = make_uint2(rtfu(v0), rtfu(v1));
    } else {
        int j = idx - 32768;
        int seg = (j < 4096) ? 0 : (j < 8192 ? 1 : 2);
        int j2 = j - (seg == 0 ? 0 : (seg == 1 ? 4096 : 8192));
        int ks = j2 >> 9, t = (j2 >> 7) & 3, n = j2 & 127;
        int k = ks * 8 + t;
        float v0, v1;
        if (seg == 0)      { v0 = Wg1[(256 + k) * 128 + n]; v1 = Wg1[(260 + k) * 128 + n]; }
        else if (seg == 1) { v0 = Wm1[(128 + k) * 128 + n]; v1 = Wm1[(132 + k) * 128 + n]; }
        else               { v0 = Wm2[k * 128 + n];         v1 = Wm2[(k + 4) * 128 + n]; }
        g_WE[j] = make_uint2(rtfu(v0), rtfu(v1));
    }
}

// ---------------- Kernel 0b: node weights ----------------
__global__ void prep_wt2_kernel(const float* __restrict__ Wagg,
                                const float* __restrict__ Wf1,
                                const float* __restrict__ Wf2) {
    int idx = blockIdx.x * 256 + threadIdx.x;
    if (idx >= 40960) return;
    float v0, v1;
    if (idx < 8192) {
        int ks = idx >> 9, t = (idx >> 7) & 3, n = idx & 127;
        int k = ks * 8 + t;
        v0 = Wagg[k * 128 + n]; v1 = Wagg[(k + 4) * 128 + n];
        g_WN[idx] = make_uint2(rtfu(v0), rtfu(v1));
    } else if (idx < 24576) {
        int j = idx - 8192;
        int ks = j >> 10, t = (j >> 8) & 3, n = j & 255;
        int k = ks * 8 + t;
        v0 = Wf1[k * 256 + n]; v1 = Wf1[(k + 4) * 256 + n];
        g_WN[idx] = make_uint2(rtfu(v0), rtfu(v1));
    } else {
        int j = idx - 24576;
        int ks = j >> 9, t = (j >> 7) & 3, n = j & 127;
        int k = ks * 8 + t;
        v0 = Wf2[k * 128 + n]; v1 = Wf2[(k + 4) * 128 + n];
        g_WN[idx] = make_uint2(rtfu(v0), rtfu(v1));
    }
}

// ---------------- Kernel 1: LN(x) -> g_h; zero cnt ----------------
__global__ void ln1_zero_kernel(const float* __restrict__ x,
                                const float* __restrict__ g, const float* __restrict__ b, int n) {
    int row = blockIdx.x * 8 + (threadIdx.x >> 5);
    int lane = threadIdx.x & 31;
    if (row >= n) return;
    float4 v = ((const float4*)(x + (size_t)row * HDIM))[lane];
    float s = v.x + v.y + v.z + v.w;
#pragma unroll
    for (int o = 16; o; o >>= 1) s += __shfl_xor_sync(0xffffffffu, s, o);
    float m = s * (1.0f / 128.0f);
    float dx = v.x - m, dy = v.y - m, dz = v.z - m, dw = v.w - m;
    float q = dx * dx + dy * dy + dz * dz + dw * dw;
#pragma unroll
    for (int o = 16; o; o >>= 1) q += __shfl_xor_sync(0xffffffffu, q, o);
    float rstd = rsqrtf(q * (1.0f / 128.0f) + 1e-5f);
    float4 gv = ((const float4*)g)[lane];
    float4 bv = ((const float4*)b)[lane];
    float4 h;
    h.x = dx * rstd * gv.x + bv.x;
    h.y = dy * rstd * gv.y + bv.y;
    h.z = dz * rstd * gv.z + bv.z;
    h.w = dw * rstd * gv.w + bv.w;
    ((float4*)(g_h + (size_t)row * HDIM))[lane] = h;
    if (lane == 0) g_cnt[row] = 0;
}

// ---------------- CSR build ----------------
__global__ void hist_kernel(const int* __restrict__ edst, int E_) {
    int i = blockIdx.x * 256 + threadIdx.x;
    if (i < E_) atomicAdd(&g_cnt[edst[i]], 1);
}
__global__ void scan1_kernel(int n) {
    __shared__ int wsum[8];
    int i = blockIdx.x * 256 + threadIdx.x;
    int lane = threadIdx.x & 31, w = threadIdx.x >> 5;
    int v = (i < n) ? g_cnt[i] : 0;
    int s = v;
#pragma unroll
    for (int o = 1; o < 32; o <<= 1) {
        int t = __shfl_up_sync(0xffffffffu, s, o);
        if (lane >= o) s += t;
    }
    if (lane == 31) wsum[w] = s;
    __syncthreads();
    if (w == 0) {
        int t = (lane < 8) ? wsum[lane] : 0;
#pragma unroll
        for (int o = 1; o < 8; o <<= 1) {
            int u = __shfl_up_sync(0xffffffffu, t, o);
            if (lane >= o) t += u;
        }
        if (lane < 8) wsum[lane] = t;
    }
    __syncthreads();
    int excl = s - v + (w > 0 ? wsum[w - 1] : 0);
    if (i < n) g_off[i] = excl;
    if (threadIdx.x == 0) g_blk[blockIdx.x] = wsum[7];
}
__global__ void scan2_kernel(int B) {
    __shared__ int wsum[8];
    int tid = threadIdx.x;
    int lane = tid & 31, w = tid >> 5;
    int v = (tid < B) ? g_blk[tid] : 0;
    int s = v;
#pragma unroll
    for (int o = 1; o < 32; o <<= 1) {
        int t = __shfl_up_sync(0xffffffffu, s, o);
        if (lane >= o) s += t;
    }
    if (lane == 31) wsum[w] = s;
    __syncthreads();
    if (w == 0) {
        int t = (lane < 8) ? wsum[lane] : 0;
#pragma unroll
        for (int o = 1; o < 8; o <<= 1) {
            int u = __shfl_up_sync(0xffffffffu, t, o);
            if (lane >= o) t += u;
        }
        if (lane < 8) wsum[lane] = t;
    }
    __syncthreads();
    int excl = s - v + (w > 0 ? wsum[w - 1] : 0);
    if (tid < B) g_blk[tid] = excl;
}
__global__ void scan3_kernel(int n) {
    int i = blockIdx.x * 256 + threadIdx.x;
    if (i < n) {
        int o = g_off[i] + g_blk[blockIdx.x];
        g_off[i] = o;
        g_cur[i] = o;
    }
}
__global__ void fill_kernel(const int* __restrict__ edst, int E_) {
    int i = blockIdx.x * 256 + threadIdx.x;
    if (i < E_) {
        int pos = atomicAdd(&g_cur[edst[i]], 1);
        g_eid[pos] = i;
    }
}

// ---------------- Kernel 2: P = h @ [Wg1a|Wg1b|Wm1a|Wself] + folded biases ----------------
// bias fold: y==0 -> +bg1 (gate dst part); y==2 -> +bm1; y==3 -> +bself+bagg
#define PLDA 132
#define PRows 64
__global__ __launch_bounds__(128, 4) void pcomp_kernel(
    const float* __restrict__ bg1, const float* __restrict__ bm1,
    const float* __restrict__ bself, const float* __restrict__ bagg, int n) {
    extern __shared__ float As[];   // 64 x 132
    int tid = threadIdx.x, lane = tid & 31, wid = tid >> 5;
    int g = lane >> 2, t = lane & 3;
    int rbase = (wid >> 1) * 32, cbase = (wid & 1) * 64;
    int n0 = blockIdx.x * PRows;
    int y = blockIdx.y;
    int wcol = y * 128 + cbase;

    for (int idx = tid; idx < PRows * 32; idx += 128) {
        int r = idx >> 5, q = idx & 31;
        int nn = n0 + r; if (nn >= n) nn = n - 1;
        float4 v = ((const float4*)(g_h + (size_t)nn * HDIM))[q];
        float* dst = As + r * PLDA + q * 4;
        dst[0] = rtf(v.x); dst[1] = rtf(v.y); dst[2] = rtf(v.z); dst[3] = rtf(v.w);
    }
    __syncthreads();

    float D[2][8][4];
    zeroD(D);
    wgemm2<PLDA, 512>(D, As, 0, 16, g_WP, wcol, rbase, g, t);

#pragma unroll
    for (int mt = 0; mt < 2; ++mt) {
        int r0 = rbase + mt * 16 + g;
        int rr0 = n0 + r0, rr1 = rr0 + 8;
#pragma unroll
        for (int nt = 0; nt < 8; ++nt) {
            int c = wcol + nt * 8 + t * 2;
            int cl = c & 127;
            float b0 = 0.f, b1 = 0.f;
            if (y == 0) { b0 = __ldg(bg1 + cl); b1 = __ldg(bg1 + cl + 1); }
            else if (y == 2) { b0 = __ldg(bm1 + cl); b1 = __ldg(bm1 + cl + 1); }
            else if (y == 3) {
                b0 = __ldg(bself + cl) + __ldg(bagg + cl);
                b1 = __ldg(bself + cl + 1) + __ldg(bagg + cl + 1);
            }
            if (rr0 < n) *(float2*)(g_P + (size_t)rr0 * 512 + c) = make_float2(D[mt][nt][0] + b0, D[mt][nt][1] + b1);
            if (rr1 < n) *(float2*)(g_P + (size_t)rr1 * 512 + c) = make_float2(D[mt][nt][2] + b0, D[mt][nt][3] + b1);
        }
    }
}

// ---------------- Kernel 3: edge MLPs (64 edges / 128 threads) ----------------
#define EA 68
#define ER 64
__global__ __launch_bounds__(128, 4) void edge_kernel(
    const int* __restrict__ esrc, const int* __restrict__ edst,
    const float* __restrict__ eemb,
    const float* __restrict__ Wg2, const float* __restrict__ bg2,
    const float* __restrict__ bm2,
    float* __restrict__ out_edge, int E_) {
    extern __shared__ float sm[];
    float* Ae = sm;                   // 64 x 68
    float* DS = sm + ER * EA;         // 64 x 132
    float* gs = DS + ER * DSL;        // 64
    int* esm = (int*)(gs + ER);
    int* edm = esm + ER;

    int tid = threadIdx.x, lane = tid & 31, wid = tid >> 5;
    int g = lane >> 2, t = lane & 3;
    int rbase = (wid >> 1) * 32, cbase = (wid & 1) * 64;
    long long e0 = (long long)blockIdx.x * ER;

    if (tid < ER) {
        long long eg = e0 + tid;
        int cl = (eg < E_) ? (int)eg : (E_ - 1);
        esm[tid] = esrc[cl]; edm[tid] = edst[cl];
    }
    __syncthreads();

    for (int idx = tid; idx < ER * 16; idx += 128) {
        int r = idx >> 4, q = idx & 15;
        long long eg = e0 + r; if (eg >= E_) eg = E_ - 1;
        float4 v = ((const float4*)(eemb + eg * 64))[q];
        float* dst = Ae + r * EA + q * 4;
        dst[0] = rtf(v.x); dst[1] = rtf(v.y); dst[2] = rtf(v.z); dst[3] = rtf(v.w);
    }
    __syncthreads();

    float D[2][8][4];

    // ---- GEMM1: gate e-part -> DS ----
    zeroD(D);
    wgemm2<EA, 128>(D, Ae, 0, 8, g_WE, cbase, rbase, g, t);
    storeD(D, DS, rbase, cbase, g, t);
    __syncthreads();

    // ---- gate pass (warp per row; bg1 folded into P[0:128]) ----
    for (int r = wid; r < ER; r += 4) {
        const float* Pd = g_P + (size_t)edm[r] * 512;
        const float* Ps = g_P + (size_t)esm[r] * 512 + 128;
        float4 de = *(const float4*)(DS + r * DSL + lane * 4);
        float4 pd = __ldg((const float4*)(Pd + lane * 4));
        float4 ps = __ldg((const float4*)(Ps + lane * 4));
        float4 ww = __ldg((const float4*)(Wg2 + lane * 4));
        float s = gelu_f(de.x + pd.x + ps.x) * ww.x
                + gelu_f(de.y + pd.y + ps.y) * ww.y
                + gelu_f(de.z + pd.z + ps.z) * ww.z
                + gelu_f(de.w + pd.w + ps.w) * ww.w;
#pragma unroll
        for (int o = 16; o; o >>= 1) s += __shfl_xor_sync(0xffffffffu, s, o);
        if (lane == 0) gs[r] = s;
    }
    __syncthreads();

    // ---- GEMM2: msg1 e-part -> DS ----
    zeroD(D);
    wgemm2<EA, 128>(D, Ae, 0, 8, g_WE + 4096, cbase, rbase, g, t);
    storeD(D, DS, rbase, cbase, g, t);
    __syncthreads();

    // ---- msg1 pass: Z (bm1 folded into P[256:384]) ----
    for (int r = wid; r < ER; r += 4) {
        const float* Pm = g_P + (size_t)esm[r] * 512 + 256;
        float* row = DS + r * DSL + lane * 4;
        float4 d = *(const float4*)row;
        float4 pm = __ldg((const float4*)(Pm + lane * 4));
        *(float4*)row = make_float4(rtf(gelu_f(d.x + pm.x)),
                                    rtf(gelu_f(d.y + pm.y)),
                                    rtf(gelu_f(d.z + pm.z)),
                                    rtf(gelu_f(d.w + pm.w)));
    }
    __syncthreads();

    // ---- GEMM3: msg2 = Z @ Wm2 ----
    zeroD(D);
    wgemm2<DSL, 128>(D, DS, 0, 16, g_WE + 8192, cbase, rbase, g, t);
    __syncthreads();
    storeD(D, DS, rbase, cbase, g, t);
    __syncthreads();

    // ---- final pass ----
    float bg2v = __ldg(bg2);
    for (int r = wid; r < ER; r += 4) {
        long long eg = e0 + r;
        if (eg >= E_) continue;
        float gt = 1.0f / (1.0f + expf(-(gs[r] + bg2v)));
        float4 d = *(const float4*)(DS + r * DSL + lane * 4);
        float4 bb = __ldg((const float4*)(bm2 + lane * 4));
        *(float4*)(out_edge + eg * 128 + lane * 4) =
            make_float4((d.x + bb.x) * gt, (d.y + bb.y) * gt,
                        (d.z + bb.z) * gt, (d.w + bb.w) * gt);
    }
}

// ---------------- Kernel 4: node update + FFN (32 nodes / 128 threads) ----------------
#define NR 32
__global__ __launch_bounds__(128, 4) void node_kernel(
    const float* __restrict__ x, const float* __restrict__ out_edge,
    const float* __restrict__ ln2g,  const float* __restrict__ ln2b,
    const float* __restrict__ bf1,   const float* __restrict__ bf2,
    float* __restrict__ out, int n) {
    extern __shared__ float sm[];
    float* AS  = sm;                    // 32x132
    float* OUT = AS + NR * DSL;         // 32x128
    float* B2  = OUT + NR * 128;        // 32x132
    float* muv = B2 + NR * DSL;
    float* rsv = muv + NR;

    int tid = threadIdx.x, lane = tid & 31, wid = tid >> 5;
    int g = lane >> 2, t = lane & 3;
    int wcol = wid * 32;                // 4 warps x 32 cols, all rows 0-31
    int n0 = blockIdx.x * NR;

    // ---- CSR gather: AG = mean of incoming edge_repr rows (tf32), 4-way ILP ----
    for (int r = wid; r < NR; r += 4) {
        int nn = n0 + r; if (nn >= n) nn = n - 1;
        int off = __ldg(&g_off[nn]);
        int c   = __ldg(&g_cnt[nn]);
        float4 a0 = make_float4(0.f, 0.f, 0.f, 0.f);
        float4 a1 = make_float4(0.f, 0.f, 0.f, 0.f);
        float4 a2 = make_float4(0.f, 0.f, 0.f, 0.f);
        float4 a3 = make_float4(0.f, 0.f, 0.f, 0.f);
        int j = 0;
        for (; j + 3 < c; j += 4) {
            int e0 = __ldg(&g_eid[off + j]),     e1 = __ldg(&g_eid[off + j + 1]);
            int e2 = __ldg(&g_eid[off + j + 2]), e3 = __ldg(&g_eid[off + j + 3]);
            float4 v0 = __ldg((const float4*)(out_edge + (size_t)e0 * 128 + lane * 4));
            float4 v1 = __ldg((const float4*)(out_edge + (size_t)e1 * 128 + lane * 4));
            float4 v2 = __ldg((const float4*)(out_edge + (size_t)e2 * 128 + lane * 4));
            float4 v3 = __ldg((const float4*)(out_edge + (size_t)e3 * 128 + lane * 4));
            a0.x += v0.x; a0.y += v0.y; a0.z += v0.z; a0.w += v0.w;
            a1.x += v1.x; a1.y += v1.y; a1.z += v1.z; a1.w += v1.w;
            a2.x += v2.x; a2.y += v2.y; a2.z += v2.z; a2.w += v2.w;
            a3.x += v3.x; a3.y += v3.y; a3.z += v3.z; a3.w += v3.w;
        }
        for (; j < c; ++j) {
            int e0 = __ldg(&g_eid[off + j]);
            float4 v0 = __ldg((const float4*)(out_edge + (size_t)e0 * 128 + lane * 4));
            a0.x += v0.x; a0.y += v0.y; a0.z += v0.z; a0.w += v0.w;
        }
        float inv = 1.0f / fmaxf((float)c, 1.0f);
        float* dst = AS + r * DSL + lane * 4;
        dst[0] = rtf((a0.x + a1.x + a2.x + a3.x) * inv);
        dst[1] = rtf((a0.y + a1.y + a2.y + a3.y) * inv);
        dst[2] = rtf((a0.z + a1.z + a2.z + a3.z) * inv);
        dst[3] = rtf((a0.w + a1.w + a2.w + a3.w) * inv);
    }
    __syncthreads();

    float D4[2][4][4];
    zeroD4(D4);
    wgemm2n<DSL, 128>(D4, AS, 16, g_WN + WAGG, wcol, 0, g, t);
    __syncthreads();
    storeD4(D4, AS, 0, wcol, g, t);
    __syncthreads();

    // ---- OUT = D + x + P[384:512] (biases folded into P) ----
    for (int r = wid; r < NR; r += 4) {
        int nn = n0 + r; int nc = (nn < n) ? nn : (n - 1);
        float4 d  = *(const float4*)(AS + r * DSL + lane * 4);
        float4 xv = __ldg((const float4*)(x + (size_t)nc * HDIM + lane * 4));
        float4 pv = __ldg((const float4*)(g_P + (size_t)nc * 512 + 384 + lane * 4));
        *(float4*)(OUT + r * 128 + lane * 4) =
            make_float4(d.x + xv.x + pv.x, d.y + xv.y + pv.y,
                        d.z + xv.z + pv.z, d.w + xv.w + pv.w);
    }
    __syncthreads();

    // ---- LN2 stats ----
    for (int r = wid; r < NR; r += 4) {
        float4 v = *(const float4*)(OUT + r * 128 + lane * 4);
        float s = v.x + v.y + v.z + v.w;
#pragma unroll
        for (int o = 16; o; o >>= 1) s += __shfl_xor_sync(0xffffffffu, s, o);
        float m = s * (1.0f / 128.0f);
        float d0 = v.x - m, d1 = v.y - m, d2 = v.z - m, d3 = v.w - m;
        float q = d0 * d0 + d1 * d1 + d2 * d2 + d3 * d3;
#pragma unroll
        for (int o = 16; o; o >>= 1) q += __shfl_xor_sync(0xffffffffu, q, o);
        if (lane == 0) { muv[r] = m; rsv[r] = rsqrtf(q * (1.0f / 128.0f) + 1e-5f); }
    }
    __syncthreads();

    // ---- TH = rtf(LN2(OUT)) -> AS ----
    for (int idx = tid; idx < NR * 128; idx += 128) {
        int r = idx >> 7, c = idx & 127;
        AS[r * DSL + c] = rtf((OUT[r * 128 + c] - muv[r]) * rsv[r] * __ldg(ln2g + c) + __ldg(ln2b + c));
    }
    __syncthreads();

    // ---- FFN ----
    float cf[2][4][4];
    zeroD4(cf);
#pragma unroll 1
    for (int h = 0; h < 2; ++h) {
        float c2[2][4][4];
        zeroD4(c2);
        wgemm2n<DSL, 256>(c2, AS, 16, g_WN + WF1, h * 128 + wcol, 0, g, t);
        __syncthreads();
#pragma unroll
        for (int mt = 0; mt < 2; ++mt) {
            int r0 = mt * 16 + g, r1 = r0 + 8;
#pragma unroll
            for (int nt = 0; nt < 4; ++nt) {
                int c = wcol + nt * 8 + t * 2;
                float b0 = __ldg(bf1 + h * 128 + c), b1 = __ldg(bf1 + h * 128 + c + 1);
                *(float2*)(B2 + r0 * DSL + c) =
                    make_float2(rtf(gelu_f(c2[mt][nt][0] + b0)), rtf(gelu_f(c2[mt][nt][1] + b1)));
                *(float2*)(B2 + r1 * DSL + c) =
                    make_float2(rtf(gelu_f(c2[mt][nt][2] + b0)), rtf(gelu_f(c2[mt][nt][3] + b1)));
            }
        }
        __syncthreads();
        wgemm2n<DSL, 128>(cf, B2, 16, g_WN + WF2 + h * 8192, wcol, 0, g, t);
    }
    storeD4(cf, AS, 0, wcol, g, t);
    __syncthreads();

    // ---- final ----
    for (int r = wid; r < NR; r += 4) {
        int nn = n0 + r;
        if (nn >= n) continue;
        float4 d = *(const float4*)(AS + r * DSL + lane * 4);
        float4 b = __ldg((const float4*)(bf2 + lane * 4));
        float4 o = *(const float4*)(OUT + r * 128 + lane * 4);
        *(float4*)(out + (size_t)nn * HDIM + lane * 4) =
            make_float4(d.x + b.x + o.x, d.y + b.y + o.y, d.z + b.z + o.z, d.w + b.w + o.w);
    }
}

// ---------------- launch ----------------
extern "C" void kernel_launch(void* const* d_in, const int* in_sizes, int n_in,
                              void* d_out, int out_size) {
    const float* x     = (const float*)d_in[0];
    const int*   esrc  = (const int*)d_in[1];
    const int*   edst  = (const int*)d_in[2];
    const float* eemb  = (const float*)d_in[3];
    const float* ln1g  = (const float*)d_in[4];
    const float* ln1b  = (const float*)d_in[5];
    const float* Wself = (const float*)d_in[6];
    const float* bself = (const float*)d_in[7];
    const float* Wm1   = (const float*)d_in[8];
    const float* bm1   = (const float*)d_in[9];
    const float* Wm2   = (const float*)d_in[10];
    const float* bm2   = (const float*)d_in[11];
    const float* Wg1   = (const float*)d_in[12];
    const float* bg1   = (const float*)d_in[13];
    const float* Wg2   = (const float*)d_in[14];
    const float* bg2   = (const float*)d_in[15];
    const float* Wagg  = (const float*)d_in[16];
    const float* bagg  = (const float*)d_in[17];
    const float* ln2g  = (const float*)d_in[18];
    const float* ln2b  = (const float*)d_in[19];
    const float* Wf1   = (const float*)d_in[20];
    const float* bf1   = (const float*)d_in[21];
    const float* Wf2   = (const float*)d_in[22];
    const float* bf2   = (const float*)d_in[23];

    int n = in_sizes[0] / HDIM;
    int E = in_sizes[1];
    float* out      = (float*)d_out;
    float* out_edge = out + (size_t)n * HDIM;
    int B = (n + 255) / 256;

    const int PC_SMEM   = PRows * PLDA * 4;
    const int EDGE_SMEM = (ER * EA + ER * DSL + ER) * 4 + ER * 4 * 2;
    const int NODE_SMEM = (NR * DSL * 2 + NR * 128 + 2 * NR) * 4;
    cudaFuncSetAttribute(pcomp_kernel, cudaFuncAttributeMaxDynamicSharedMemorySize, PC_SMEM);
    cudaFuncSetAttribute(edge_kernel,  cudaFuncAttributeMaxDynamicSharedMemorySize, EDGE_SMEM);
    cudaFuncSetAttribute(node_kernel,  cudaFuncAttributeMaxDynamicSharedMemorySize, NODE_SMEM);

    // launch order keeps edge_kernel at slot 4 (profiler lands on 4th launch)
    prep_wt_kernel<<<(49152 + 255) / 256, 256>>>(Wg1, Wm1, Wm2, Wself);
    ln1_zero_kernel<<<(n + 7) / 8, 256>>>(x, ln1g, ln1b, n);
    dim3 pg((n + PRows - 1) / PRows, 4);
    pcomp_kernel<<<pg, 128, PC_SMEM>>>(bg1, bm1, bself, bagg, n);
    edge_kernel<<<(E + ER - 1) / ER, 128, EDGE_SMEM>>>(
        esrc, edst, eemb, Wg2, bg2, bm2, out_edge, E);
    hist_kernel<<<(E + 255) / 256, 256>>>(edst, E);
    scan1_kernel<<<B, 256>>>(n);
    scan2_kernel<<<1, 256>>>(B);
    scan3_kernel<<<B, 256>>>(n);
    fill_kernel<<<(E + 255) / 256, 256>>>(edst, E);
    prep_wt2_kernel<<<(40960 + 255) / 256, 256>>>(Wagg, Wf1, Wf2);
    node_kernel<<<(n + NR - 1) / NR, 128, NODE_SMEM>>>(
        x, out_edge, ln2g, ln2b, bf1, bf2, out, n);
}